// round 3
// baseline (speedup 1.0000x reference)
#include <cuda_runtime.h>
#include <cstdint>

typedef unsigned long long ull;

#define B_  8
#define NQ_ 256
#define NK_ 4096
#define C_  1024
#define H_  16
#define D_  64

// ---------------- scratch (static device globals: no allocation allowed) ----
__device__ float g_q [B_ * NQ_ * C_];            // LN(query)+query_pos     8 MB
__device__ float g_kn[B_ * NK_ * C_];            // LN(memory) == V       128 MB
__device__ float g_k [B_ * NK_ * C_];            // projected K           128 MB
__device__ float g_m [B_ * H_ * NQ_];            // row max
__device__ float g_l [B_ * H_ * NQ_];            // row sum-exp
__device__ float g_scores[(size_t)B_ * H_ * NQ_ * NK_]; // fallback if attn not in d_out

// ---------------- packed f32x2 helpers --------------------------------------
__device__ __forceinline__ ull pack2(float x, float y) {
    ull r;
    asm("mov.b64 %0, {%1, %2};" : "=l"(r)
        : "r"(__float_as_uint(x)), "r"(__float_as_uint(y)));
    return r;
}
__device__ __forceinline__ float2 unpack2(ull v) {
    unsigned lo, hi;
    asm("mov.b64 {%0, %1}, %2;" : "=r"(lo), "=r"(hi) : "l"(v));
    return make_float2(__uint_as_float(lo), __uint_as_float(hi));
}
__device__ __forceinline__ ull fma2(ull a, ull b, ull c) {
    ull d;
    asm("fma.rn.f32x2 %0, %1, %2, %3;" : "=l"(d) : "l"(a), "l"(b), "l"(c));
    return d;
}

// ---------------- LayerNorm (+ optional pos add) ----------------------------
// one block per row of 1024; 256 threads, one float4 each
__global__ __launch_bounds__(256) void ln_kernel(
    const float* __restrict__ x, const float* __restrict__ w,
    const float* __restrict__ bw, const float* __restrict__ pos,
    float* __restrict__ y)
{
    int row = blockIdx.x;
    size_t base = (size_t)row * C_;
    int t = threadIdx.x;
    float4 v = *(const float4*)(x + base + t * 4);

    float s  = v.x + v.y + v.z + v.w;
    float s2 = v.x * v.x + v.y * v.y + v.z * v.z + v.w * v.w;

    __shared__ float rs[8], rs2[8];
    int lane = t & 31, wid = t >> 5;
#pragma unroll
    for (int o = 16; o > 0; o >>= 1) {
        s  += __shfl_xor_sync(0xffffffffu, s,  o);
        s2 += __shfl_xor_sync(0xffffffffu, s2, o);
    }
    if (lane == 0) { rs[wid] = s; rs2[wid] = s2; }
    __syncthreads();
    if (t == 0) {
        float a = 0.f, b = 0.f;
#pragma unroll
        for (int i = 0; i < 8; i++) { a += rs[i]; b += rs2[i]; }
        rs[0] = a; rs2[0] = b;
    }
    __syncthreads();

    float mu  = rs[0]  * (1.0f / C_);
    float var = rs2[0] * (1.0f / C_) - mu * mu;
    float inv = rsqrtf(var + 1e-5f);

    float4 wv = *(const float4*)(w  + t * 4);
    float4 bv = *(const float4*)(bw + t * 4);
    float4 o;
    o.x = (v.x - mu) * inv * wv.x + bv.x;
    o.y = (v.y - mu) * inv * wv.y + bv.y;
    o.z = (v.z - mu) * inv * wv.z + bv.z;
    o.w = (v.w - mu) * inv * wv.w + bv.w;
    if (pos) {
        float4 p = *(const float4*)(pos + base + t * 4);
        o.x += p.x; o.y += p.y; o.z += p.z; o.w += p.w;
    }
    *(float4*)(y + base + t * 4) = o;
}

// ---------------- K projection: g_k = (g_kn + mpos) @ Wk^T ------------------
// M=32768, N=1024, K=1024.  BM=BN=128, BK=16, 256 threads, 8x8/thread, FFMA2.
__global__ __launch_bounds__(256) void kproj_kernel(
    const float* __restrict__ mpos, const float* __restrict__ Wk)
{
    __shared__ float As[16][128];   // [k][m]
    __shared__ float Bs[16][128];   // [k][n]
    int tid = threadIdx.x;
    int tx = tid & 15, ty = tid >> 4;
    int m0 = blockIdx.y * 128;
    int n0 = blockIdx.x * 128;

    ull acc[8][4];
#pragma unroll
    for (int i = 0; i < 8; i++)
#pragma unroll
        for (int j = 0; j < 4; j++) acc[i][j] = 0ULL;

    for (int k0 = 0; k0 < C_; k0 += 16) {
        __syncthreads();
#pragma unroll
        for (int i = 0; i < 2; i++) {
            int idx = tid + i * 256;          // 0..511
            int r = idx >> 2, c4 = idx & 3;
            size_t g = (size_t)(m0 + r) * C_ + k0 + c4 * 4;
            float4 a = *(const float4*)(g_kn + g);
            float4 p = *(const float4*)(mpos + g);
            a.x += p.x; a.y += p.y; a.z += p.z; a.w += p.w;
            As[c4 * 4 + 0][r] = a.x; As[c4 * 4 + 1][r] = a.y;
            As[c4 * 4 + 2][r] = a.z; As[c4 * 4 + 3][r] = a.w;
        }
#pragma unroll
        for (int i = 0; i < 2; i++) {
            int idx = tid + i * 256;
            int r = idx >> 2, c4 = idx & 3;
            float4 b = *(const float4*)(Wk + (size_t)(n0 + r) * C_ + k0 + c4 * 4);
            Bs[c4 * 4 + 0][r] = b.x; Bs[c4 * 4 + 1][r] = b.y;
            Bs[c4 * 4 + 2][r] = b.z; Bs[c4 * 4 + 3][r] = b.w;
        }
        __syncthreads();

#pragma unroll
        for (int kk = 0; kk < 16; kk++) {
            float4 a0 = *(const float4*)&As[kk][ty * 8];
            float4 a1 = *(const float4*)&As[kk][ty * 8 + 4];
            float4 b0 = *(const float4*)&Bs[kk][tx * 8];
            float4 b1 = *(const float4*)&Bs[kk][tx * 8 + 4];
            ull bb[4] = { pack2(b0.x, b0.y), pack2(b0.z, b0.w),
                          pack2(b1.x, b1.y), pack2(b1.z, b1.w) };
            float av[8] = { a0.x, a0.y, a0.z, a0.w, a1.x, a1.y, a1.z, a1.w };
#pragma unroll
            for (int i = 0; i < 8; i++) {
                ull ap = pack2(av[i], av[i]);
#pragma unroll
                for (int j = 0; j < 4; j++)
                    acc[i][j] = fma2(ap, bb[j], acc[i][j]);
            }
        }
    }

#pragma unroll
    for (int i = 0; i < 8; i++) {
        size_t row = (size_t)(m0 + ty * 8 + i) * C_ + n0 + tx * 8;
        float2 p0 = unpack2(acc[i][0]), p1 = unpack2(acc[i][1]);
        float2 p2 = unpack2(acc[i][2]), p3 = unpack2(acc[i][3]);
        *(float4*)&g_k[row]     = make_float4(p0.x, p0.y, p1.x, p1.y);
        *(float4*)&g_k[row + 4] = make_float4(p2.x, p2.y, p3.x, p3.y);
    }
}

// ---------------- QK^T + bias + mask -> raw scores, online (m, l) -----------
// grid (NQ/64, H, B); 256 threads as 16x16, 4x4 per thread over a 64x64 tile
// mask arrives as int32 (numpy bool promoted by the harness)
__global__ __launch_bounds__(256) void qk_kernel(
    const float* __restrict__ bias, const int* __restrict__ mask,
    float* __restrict__ scores)
{
    int b = blockIdx.z, h = blockIdx.y, q0 = blockIdx.x * 64;
    __shared__ float Qs[64][68];   // [d][q]
    __shared__ float Ks[64][68];   // [d][k]
    __shared__ int Ms[64];

    int tid = threadIdx.x;
    int tx = tid & 15, ty = tid >> 4;

    // load Q tile transposed
#pragma unroll
    for (int i = 0; i < 4; i++) {
        int idx = tid + i * 256;               // 0..1023
        int r = idx >> 4, c4 = idx & 15;
        float4 v = *(const float4*)(g_q + (size_t)(b * NQ_ + q0 + r) * C_ + h * D_ + c4 * 4);
        Qs[c4 * 4 + 0][r] = v.x; Qs[c4 * 4 + 1][r] = v.y;
        Qs[c4 * 4 + 2][r] = v.z; Qs[c4 * 4 + 3][r] = v.w;
    }

    float m_run[4] = { -1e30f, -1e30f, -1e30f, -1e30f };
    float l_run[4] = { 0.f, 0.f, 0.f, 0.f };

    for (int k0 = 0; k0 < NK_; k0 += 64) {
        __syncthreads();
#pragma unroll
        for (int i = 0; i < 4; i++) {
            int idx = tid + i * 256;
            int r = idx >> 4, c4 = idx & 15;
            float4 v = *(const float4*)(g_k + (size_t)(b * NK_ + k0 + r) * C_ + h * D_ + c4 * 4);
            Ks[c4 * 4 + 0][r] = v.x; Ks[c4 * 4 + 1][r] = v.y;
            Ks[c4 * 4 + 2][r] = v.z; Ks[c4 * 4 + 3][r] = v.w;
        }
        if (tid < 64) Ms[tid] = mask[b * NK_ + k0 + tid];
        __syncthreads();

        ull acc2[4][2];
#pragma unroll
        for (int i = 0; i < 4; i++) { acc2[i][0] = 0ULL; acc2[i][1] = 0ULL; }

#pragma unroll
        for (int d = 0; d < 64; d++) {
            float4 aq = *(const float4*)&Qs[d][ty * 4];
            float4 bk = *(const float4*)&Ks[d][tx * 4];
            ull b20 = pack2(bk.x, bk.y);
            ull b21 = pack2(bk.z, bk.w);
            float aa[4] = { aq.x, aq.y, aq.z, aq.w };
#pragma unroll
            for (int i = 0; i < 4; i++) {
                ull ap = pack2(aa[i], aa[i]);
                acc2[i][0] = fma2(ap, b20, acc2[i][0]);
                acc2[i][1] = fma2(ap, b21, acc2[i][1]);
            }
        }

        // scale + bias + mask, write raw scores, online m/l
#pragma unroll
        for (int i = 0; i < 4; i++) {
            float2 f0 = unpack2(acc2[i][0]);
            float2 f1 = unpack2(acc2[i][1]);
            float s[4] = { f0.x, f0.y, f1.x, f1.y };
            size_t gaddr = ((size_t)((b * H_ + h) * NQ_ + q0 + ty * 4 + i)) * NK_ + k0 + tx * 4;
            float4 bv = *(const float4*)(bias + gaddr);
            float bb4[4] = { bv.x, bv.y, bv.z, bv.w };
#pragma unroll
            for (int j = 0; j < 4; j++) {
                s[j] = s[j] * 0.125f + bb4[j];
                if (Ms[tx * 4 + j]) s[j] = -1e9f;
            }
            *(float4*)(scores + gaddr) = make_float4(s[0], s[1], s[2], s[3]);

            float tmax = fmaxf(fmaxf(s[0], s[1]), fmaxf(s[2], s[3]));
#pragma unroll
            for (int o = 1; o < 16; o <<= 1)
                tmax = fmaxf(tmax, __shfl_xor_sync(0xffffffffu, tmax, o, 16));
            float mn = fmaxf(m_run[i], tmax);
            float tsum = __expf(s[0] - mn) + __expf(s[1] - mn)
                       + __expf(s[2] - mn) + __expf(s[3] - mn);
#pragma unroll
            for (int o = 1; o < 16; o <<= 1)
                tsum += __shfl_xor_sync(0xffffffffu, tsum, o, 16);
            l_run[i] = l_run[i] * __expf(m_run[i] - mn) + tsum;
            m_run[i] = mn;
        }
    }

    if (tx == 0) {
#pragma unroll
        for (int i = 0; i < 4; i++) {
            int row = (b * H_ + h) * NQ_ + q0 + ty * 4 + i;
            g_m[row] = m_run[i];
            g_l[row] = l_run[i];
        }
    }
}

// ---------------- normalize + attn write + A@V + residual -------------------
// grid (NQ/64, H, B); 256 threads: thread = (q=tid>>2, g=tid&3), g owns 16 d's
__global__ __launch_bounds__(256) void av_kernel(
    const float* __restrict__ scores_in, const float* __restrict__ query,
    float* __restrict__ attn_out, float* __restrict__ out0)
{
    int b = blockIdx.z, h = blockIdx.y, q0 = blockIdx.x * 64;
    __shared__ float Ps[64][68];
    __shared__ float Vs[64][68];
    __shared__ float Mv[64], Li[64];

    int tid = threadIdx.x;
    int qid = tid >> 2, g = tid & 3;

    if (tid < 64) {
        int row = (b * H_ + h) * NQ_ + q0 + tid;
        Mv[tid] = g_m[row];
        Li[tid] = 1.0f / g_l[row];
    }

    ull acc2[8];
#pragma unroll
    for (int j = 0; j < 8; j++) acc2[j] = 0ULL;

    for (int k0 = 0; k0 < NK_; k0 += 64) {
        __syncthreads();
        // scores -> p, write attn, stage into Ps
#pragma unroll
        for (int i = 0; i < 4; i++) {
            int idx = tid + i * 256;
            int r = idx >> 4, c4 = idx & 15;
            size_t gaddr = ((size_t)((b * H_ + h) * NQ_ + q0 + r)) * NK_ + k0 + c4 * 4;
            float4 s = *(const float4*)(scores_in + gaddr);
            float mm = Mv[r], li = Li[r];
            float4 p;
            p.x = __expf(s.x - mm) * li;
            p.y = __expf(s.y - mm) * li;
            p.z = __expf(s.z - mm) * li;
            p.w = __expf(s.w - mm) * li;
            *(float4*)(attn_out + gaddr) = p;
            *(float4*)&Ps[r][c4 * 4] = p;
        }
        // V tile (natural layout [k][d])
#pragma unroll
        for (int i = 0; i < 4; i++) {
            int idx = tid + i * 256;
            int r = idx >> 4, c4 = idx & 15;
            float4 v = *(const float4*)(g_kn + (size_t)(b * NK_ + k0 + r) * C_ + h * D_ + c4 * 4);
            *(float4*)&Vs[r][c4 * 4] = v;
        }
        __syncthreads();

#pragma unroll 8
        for (int kk = 0; kk < 64; kk++) {
            float pv = Ps[qid][kk];
            ull pp = pack2(pv, pv);
#pragma unroll
            for (int j = 0; j < 4; j++) {
                ull v0 = *(const ull*)&Vs[kk][16 * j + 4 * g];
                ull v1 = *(const ull*)&Vs[kk][16 * j + 4 * g + 2];
                acc2[2 * j]     = fma2(pp, v0, acc2[2 * j]);
                acc2[2 * j + 1] = fma2(pp, v1, acc2[2 * j + 1]);
            }
        }
    }

    if (out0) {
#pragma unroll
        for (int j = 0; j < 4; j++) {
            float2 f0 = unpack2(acc2[2 * j]);
            float2 f1 = unpack2(acc2[2 * j + 1]);
            size_t o = (size_t)(b * NQ_ + q0 + qid) * C_ + h * D_ + 16 * j + 4 * g;
            float4 qv = *(const float4*)(query + o);
            *(float4*)(out0 + o) = make_float4(qv.x + f0.x, qv.y + f0.y,
                                               qv.z + f1.x, qv.w + f1.y);
        }
    }
}

// ---------------- host ------------------------------------------------------
extern "C" void kernel_launch(void* const* d_in, const int* in_sizes, int n_in,
                              void* d_out, int out_size)
{
    const float* query  = (const float*)d_in[0];
    const float* memory = (const float*)d_in[1];
    const float* qpos   = (const float*)d_in[2];
    const float* mpos   = (const float*)d_in[3];
    const float* bias   = (const float*)d_in[4];
    const int*   mask   = (const int*)d_in[5];      // bool promoted to int32
    const float* Wk     = (const float*)d_in[6];
    const float* lnqw   = (const float*)d_in[7];
    const float* lnqb   = (const float*)d_in[8];
    const float* lnkw   = (const float*)d_in[9];
    const float* lnkb   = (const float*)d_in[10];
    (void)in_sizes; (void)n_in;

    float* out = (float*)d_out;
    const long long OUT0 = (long long)B_ * NQ_ * C_;                 // 2,097,152
    const long long ATT  = (long long)B_ * H_ * NQ_ * NK_;           // 134,217,728

    float* out0 = nullptr;
    float* attn = nullptr;
    if ((long long)out_size >= OUT0 + ATT) { out0 = out; attn = out + OUT0; }
    else if ((long long)out_size >= ATT)   { attn = out; }
    else {
        out0 = out;
        cudaGetSymbolAddress((void**)&attn, g_scores);
    }

    float *gq_ptr, *gkn_ptr;
    cudaGetSymbolAddress((void**)&gq_ptr,  g_q);
    cudaGetSymbolAddress((void**)&gkn_ptr, g_kn);

    // 1) q = LN(query)*w+b + query_pos
    ln_kernel<<<B_ * NQ_, 256>>>(query, lnqw, lnqb, qpos, gq_ptr);
    // 2) kn = LN(memory)*w+b   (== V)
    ln_kernel<<<B_ * NK_, 256>>>(memory, lnkw, lnkb, nullptr, gkn_ptr);
    // 3) k = (kn + memory_pos) @ Wk^T
    {
        dim3 grid(C_ / 128, (B_ * NK_) / 128);
        kproj_kernel<<<grid, 256>>>(mpos, Wk);
    }
    // 4) raw scores + online softmax stats
    {
        dim3 grid(NQ_ / 64, H_, B_);
        qk_kernel<<<grid, 256>>>(bias, mask, attn);
    }
    // 5) normalize -> attn output, A@V, residual
    {
        dim3 grid(NQ_ / 64, H_, B_);
        av_kernel<<<grid, 256>>>(attn, query, attn, out0);
    }
}

// round 5
// speedup vs baseline: 1.2676x; 1.2676x over previous
#include <cuda_runtime.h>
#include <cuda_bf16.h>
#include <cstdint>

typedef unsigned long long ull;

#define B_  8
#define NQ_ 256
#define NK_ 4096
#define C_  1024
#define H_  16
#define D_  64

// ---------------- scratch (static device globals) ---------------------------
__device__ float g_q [B_ * NQ_ * C_];             // LN(query)+query_pos
__device__ float g_kn[B_ * NK_ * C_];             // LN(memory) == V
__device__ float g_k [B_ * NK_ * C_];             // projected K (f32)
__device__ float g_l [B_ * H_ * NQ_];             // row sum-exp
__device__ __nv_bfloat16 g_ahi[(size_t)B_ * NK_ * C_]; // (kn+mpos) hi
__device__ __nv_bfloat16 g_alo[(size_t)B_ * NK_ * C_]; // (kn+mpos) lo
__device__ __nv_bfloat16 g_bhi[C_ * C_];          // Wk hi
__device__ __nv_bfloat16 g_blo[C_ * C_];          // Wk lo
__device__ float g_scores[(size_t)B_ * H_ * NQ_ * NK_]; // fallback

// ---------------- packed f32x2 helpers --------------------------------------
__device__ __forceinline__ ull pack2(float x, float y) {
    ull r;
    asm("mov.b64 %0, {%1, %2};" : "=l"(r)
        : "r"(__float_as_uint(x)), "r"(__float_as_uint(y)));
    return r;
}
__device__ __forceinline__ float2 unpack2(ull v) {
    unsigned lo, hi;
    asm("mov.b64 {%0, %1}, %2;" : "=r"(lo), "=r"(hi) : "l"(v));
    return make_float2(__uint_as_float(lo), __uint_as_float(hi));
}
__device__ __forceinline__ ull fma2(ull a, ull b, ull c) {
    ull d;
    asm("fma.rn.f32x2 %0, %1, %2, %3;" : "=l"(d) : "l"(a), "l"(b), "l"(c));
    return d;
}

// ---------------- mma.sync helpers (arch-neutral, works on .target sm_103) --
__device__ __forceinline__ uint32_t smem_u32(const void* p) {
    uint32_t a;
    asm("{ .reg .u64 t; cvta.to.shared.u64 t, %1; cvt.u32.u64 %0, t; }"
        : "=r"(a) : "l"(p));
    return a;
}
__device__ __forceinline__ void ldsm_x4(uint32_t& r0, uint32_t& r1,
                                        uint32_t& r2, uint32_t& r3, uint32_t addr) {
    asm volatile("ldmatrix.sync.aligned.m8n8.x4.shared.b16 {%0,%1,%2,%3}, [%4];"
                 : "=r"(r0), "=r"(r1), "=r"(r2), "=r"(r3) : "r"(addr));
}
__device__ __forceinline__ void mma16816(float* d, const uint32_t* a,
                                         uint32_t b0, uint32_t b1) {
    asm volatile(
        "mma.sync.aligned.m16n8k16.row.col.f32.bf16.bf16.f32 "
        "{%0,%1,%2,%3}, {%4,%5,%6,%7}, {%8,%9}, {%0,%1,%2,%3};"
        : "+f"(d[0]), "+f"(d[1]), "+f"(d[2]), "+f"(d[3])
        : "r"(a[0]), "r"(a[1]), "r"(a[2]), "r"(a[3]), "r"(b0), "r"(b1));
}

// ---------------- LayerNorm for query (+pos) --------------------------------
__global__ __launch_bounds__(256) void ln_kernel(
    const float* __restrict__ x, const float* __restrict__ w,
    const float* __restrict__ bw, const float* __restrict__ pos,
    float* __restrict__ y)
{
    int row = blockIdx.x;
    size_t base = (size_t)row * C_;
    int t = threadIdx.x;
    float4 v = *(const float4*)(x + base + t * 4);

    float s  = v.x + v.y + v.z + v.w;
    float s2 = v.x * v.x + v.y * v.y + v.z * v.z + v.w * v.w;

    __shared__ float rs[8], rs2[8];
    int lane = t & 31, wid = t >> 5;
#pragma unroll
    for (int o = 16; o > 0; o >>= 1) {
        s  += __shfl_xor_sync(0xffffffffu, s,  o);
        s2 += __shfl_xor_sync(0xffffffffu, s2, o);
    }
    if (lane == 0) { rs[wid] = s; rs2[wid] = s2; }
    __syncthreads();
    if (t == 0) {
        float a = 0.f, b = 0.f;
#pragma unroll
        for (int i = 0; i < 8; i++) { a += rs[i]; b += rs2[i]; }
        rs[0] = a; rs2[0] = b;
    }
    __syncthreads();

    float mu  = rs[0]  * (1.0f / C_);
    float var = rs2[0] * (1.0f / C_) - mu * mu;
    float inv = rsqrtf(var + 1e-5f);

    float4 wv = *(const float4*)(w  + t * 4);
    float4 bv = *(const float4*)(bw + t * 4);
    float4 o;
    o.x = (v.x - mu) * inv * wv.x + bv.x;
    o.y = (v.y - mu) * inv * wv.y + bv.y;
    o.z = (v.z - mu) * inv * wv.z + bv.z;
    o.w = (v.w - mu) * inv * wv.w + bv.w;
    if (pos) {
        float4 p = *(const float4*)(pos + base + t * 4);
        o.x += p.x; o.y += p.y; o.z += p.z; o.w += p.w;
    }
    *(float4*)(y + base + t * 4) = o;
}

// ---------------- LayerNorm for memory: kn (f32) + split bf16 of kn+mpos ----
__global__ __launch_bounds__(256) void ln_k_kernel(
    const float* __restrict__ x, const float* __restrict__ w,
    const float* __restrict__ bw, const float* __restrict__ pos,
    float* __restrict__ y, __nv_bfloat16* __restrict__ hi,
    __nv_bfloat16* __restrict__ lo)
{
    int row = blockIdx.x;
    size_t base = (size_t)row * C_;
    int t = threadIdx.x;
    float4 v = *(const float4*)(x + base + t * 4);

    float s  = v.x + v.y + v.z + v.w;
    float s2 = v.x * v.x + v.y * v.y + v.z * v.z + v.w * v.w;

    __shared__ float rs[8], rs2[8];
    int lane = t & 31, wid = t >> 5;
#pragma unroll
    for (int o = 16; o > 0; o >>= 1) {
        s  += __shfl_xor_sync(0xffffffffu, s,  o);
        s2 += __shfl_xor_sync(0xffffffffu, s2, o);
    }
    if (lane == 0) { rs[wid] = s; rs2[wid] = s2; }
    __syncthreads();
    if (t == 0) {
        float a = 0.f, b = 0.f;
#pragma unroll
        for (int i = 0; i < 8; i++) { a += rs[i]; b += rs2[i]; }
        rs[0] = a; rs2[0] = b;
    }
    __syncthreads();

    float mu  = rs[0]  * (1.0f / C_);
    float var = rs2[0] * (1.0f / C_) - mu * mu;
    float inv = rsqrtf(var + 1e-5f);

    float4 wv = *(const float4*)(w  + t * 4);
    float4 bv = *(const float4*)(bw + t * 4);
    float4 o;
    o.x = (v.x - mu) * inv * wv.x + bv.x;
    o.y = (v.y - mu) * inv * wv.y + bv.y;
    o.z = (v.z - mu) * inv * wv.z + bv.z;
    o.w = (v.w - mu) * inv * wv.w + bv.w;
    *(float4*)(y + base + t * 4) = o;

    float4 p = *(const float4*)(pos + base + t * 4);
    float a0 = o.x + p.x, a1 = o.y + p.y, a2 = o.z + p.z, a3 = o.w + p.w;
    __nv_bfloat16 h0 = __float2bfloat16(a0), h1 = __float2bfloat16(a1);
    __nv_bfloat16 h2 = __float2bfloat16(a2), h3 = __float2bfloat16(a3);
    __nv_bfloat16 l0 = __float2bfloat16(a0 - __bfloat162float(h0));
    __nv_bfloat16 l1 = __float2bfloat16(a1 - __bfloat162float(h1));
    __nv_bfloat16 l2 = __float2bfloat16(a2 - __bfloat162float(h2));
    __nv_bfloat16 l3 = __float2bfloat16(a3 - __bfloat162float(h3));
    *(__nv_bfloat162*)(hi + base + t * 4)     = __nv_bfloat162(h0, h1);
    *(__nv_bfloat162*)(hi + base + t * 4 + 2) = __nv_bfloat162(h2, h3);
    *(__nv_bfloat162*)(lo + base + t * 4)     = __nv_bfloat162(l0, l1);
    *(__nv_bfloat162*)(lo + base + t * 4 + 2) = __nv_bfloat162(l2, l3);
}

// ---------------- Wk split ---------------------------------------------------
__global__ __launch_bounds__(256) void wconv_kernel(
    const float* __restrict__ Wk, __nv_bfloat16* __restrict__ hi,
    __nv_bfloat16* __restrict__ lo)
{
    size_t i = (size_t)blockIdx.x * 1024 + threadIdx.x * 4;
    float4 v = *(const float4*)(Wk + i);
    __nv_bfloat16 h0 = __float2bfloat16(v.x), h1 = __float2bfloat16(v.y);
    __nv_bfloat16 h2 = __float2bfloat16(v.z), h3 = __float2bfloat16(v.w);
    __nv_bfloat16 l0 = __float2bfloat16(v.x - __bfloat162float(h0));
    __nv_bfloat16 l1 = __float2bfloat16(v.y - __bfloat162float(h1));
    __nv_bfloat16 l2 = __float2bfloat16(v.z - __bfloat162float(h2));
    __nv_bfloat16 l3 = __float2bfloat16(v.w - __bfloat162float(h3));
    *(__nv_bfloat162*)(hi + i)     = __nv_bfloat162(h0, h1);
    *(__nv_bfloat162*)(hi + i + 2) = __nv_bfloat162(h2, h3);
    *(__nv_bfloat162*)(lo + i)     = __nv_bfloat162(l0, l1);
    *(__nv_bfloat162*)(lo + i + 2) = __nv_bfloat162(l2, l3);
}

// ---------------- K projection via mma.sync (split bf16, 3-term) ------------
// g_k[m][n] = sum_k A[m][k] * Wk[n][k];  M=32768, N=1024, K=1024
// block 128x128, 8 warps (4x2), warp tile 32x64, K-chunk 32
__global__ __launch_bounds__(256) void kproj_mma(
    const __nv_bfloat16* __restrict__ ahi_g, const __nv_bfloat16* __restrict__ alo_g,
    const __nv_bfloat16* __restrict__ bhi_g, const __nv_bfloat16* __restrict__ blo_g)
{
    __shared__ __nv_bfloat16 As_h[128][40];
    __shared__ __nv_bfloat16 As_l[128][40];
    __shared__ __nv_bfloat16 Bs_h[128][40];
    __shared__ __nv_bfloat16 Bs_l[128][40];

    int tid = threadIdx.x, lane = tid & 31, wid = tid >> 5;
    int wm = wid >> 1, wn = wid & 1;
    int m0 = blockIdx.y * 128, n0 = blockIdx.x * 128;

    float acc[2][8][4];
#pragma unroll
    for (int mt = 0; mt < 2; mt++)
#pragma unroll
        for (int nt = 0; nt < 8; nt++)
#pragma unroll
            for (int e = 0; e < 4; e++) acc[mt][nt][e] = 0.f;

    // ldmatrix lane addressing
    int a_r = lane & 15;
    int a_c = (lane >> 4) << 3;
    int b_r = (lane & 7) + ((lane >> 4) << 3);
    int b_c = ((lane >> 3) & 1) << 3;

    for (int kc = 0; kc < 32; kc++) {
        __syncthreads();
#pragma unroll
        for (int i = 0; i < 2; i++) {
            int idx = tid + i * 256;            // 0..511
            int r = idx >> 2, c = (idx & 3) << 3;
            size_t ga = (size_t)(m0 + r) * C_ + kc * 32 + c;
            size_t gb = (size_t)(n0 + r) * C_ + kc * 32 + c;
            *(uint4*)&As_h[r][c] = *(const uint4*)(ahi_g + ga);
            *(uint4*)&As_l[r][c] = *(const uint4*)(alo_g + ga);
            *(uint4*)&Bs_h[r][c] = *(const uint4*)(bhi_g + gb);
            *(uint4*)&Bs_l[r][c] = *(const uint4*)(blo_g + gb);
        }
        __syncthreads();

#pragma unroll
        for (int ks = 0; ks < 2; ks++) {
            int k0 = ks * 16;
            uint32_t Ah[2][4], Al[2][4], Bf[4][4];
#pragma unroll
            for (int mt = 0; mt < 2; mt++) {
                ldsm_x4(Ah[mt][0], Ah[mt][1], Ah[mt][2], Ah[mt][3],
                        smem_u32(&As_h[wm * 32 + mt * 16 + a_r][k0 + a_c]));
                ldsm_x4(Al[mt][0], Al[mt][1], Al[mt][2], Al[mt][3],
                        smem_u32(&As_l[wm * 32 + mt * 16 + a_r][k0 + a_c]));
            }
#pragma unroll
            for (int p = 0; p < 4; p++)
                ldsm_x4(Bf[p][0], Bf[p][1], Bf[p][2], Bf[p][3],
                        smem_u32(&Bs_h[wn * 64 + p * 16 + b_r][k0 + b_c]));

            // hi*hi and lo*hi
#pragma unroll
            for (int mt = 0; mt < 2; mt++)
#pragma unroll
                for (int p = 0; p < 4; p++) {
                    mma16816(acc[mt][2 * p],     Ah[mt], Bf[p][0], Bf[p][1]);
                    mma16816(acc[mt][2 * p + 1], Ah[mt], Bf[p][2], Bf[p][3]);
                    mma16816(acc[mt][2 * p],     Al[mt], Bf[p][0], Bf[p][1]);
                    mma16816(acc[mt][2 * p + 1], Al[mt], Bf[p][2], Bf[p][3]);
                }

            // hi*lo (reload B frags as lo)
#pragma unroll
            for (int p = 0; p < 4; p++)
                ldsm_x4(Bf[p][0], Bf[p][1], Bf[p][2], Bf[p][3],
                        smem_u32(&Bs_l[wn * 64 + p * 16 + b_r][k0 + b_c]));
#pragma unroll
            for (int mt = 0; mt < 2; mt++)
#pragma unroll
                for (int p = 0; p < 4; p++) {
                    mma16816(acc[mt][2 * p],     Ah[mt], Bf[p][0], Bf[p][1]);
                    mma16816(acc[mt][2 * p + 1], Ah[mt], Bf[p][2], Bf[p][3]);
                }
        }
    }

    // write D
#pragma unroll
    for (int mt = 0; mt < 2; mt++)
#pragma unroll
        for (int nt = 0; nt < 8; nt++) {
            int row = m0 + wm * 32 + mt * 16 + (lane >> 2);
            int col = n0 + wn * 64 + nt * 8 + (lane & 3) * 2;
            *(float2*)&g_k[(size_t)row * C_ + col] =
                make_float2(acc[mt][nt][0], acc[mt][nt][1]);
            *(float2*)&g_k[(size_t)(row + 8) * C_ + col] =
                make_float2(acc[mt][nt][2], acc[mt][nt][3]);
        }
}

// ---------------- QK^T + bias + mask -> exp(scores), row sums ---------------
__global__ __launch_bounds__(256) void qk_kernel(
    const float* __restrict__ bias, const int* __restrict__ mask,
    float* __restrict__ scores)
{
    int b = blockIdx.z, h = blockIdx.y, q0 = blockIdx.x * 64;
    __shared__ float Qs[64][68];   // [d][q]
    __shared__ float Ks[64][68];   // [d][k]
    __shared__ int Ms[64];

    int tid = threadIdx.x;
    int tx = tid & 15, ty = tid >> 4;

#pragma unroll
    for (int i = 0; i < 4; i++) {
        int idx = tid + i * 256;
        int r = idx >> 4, c4 = idx & 15;
        float4 v = *(const float4*)(g_q + (size_t)(b * NQ_ + q0 + r) * C_ + h * D_ + c4 * 4);
        Qs[c4 * 4 + 0][r] = v.x; Qs[c4 * 4 + 1][r] = v.y;
        Qs[c4 * 4 + 2][r] = v.z; Qs[c4 * 4 + 3][r] = v.w;
    }

    float l_run[4] = { 0.f, 0.f, 0.f, 0.f };

    for (int k0 = 0; k0 < NK_; k0 += 64) {
        __syncthreads();
#pragma unroll
        for (int i = 0; i < 4; i++) {
            int idx = tid + i * 256;
            int r = idx >> 4, c4 = idx & 15;
            float4 v = *(const float4*)(g_k + (size_t)(b * NK_ + k0 + r) * C_ + h * D_ + c4 * 4);
            Ks[c4 * 4 + 0][r] = v.x; Ks[c4 * 4 + 1][r] = v.y;
            Ks[c4 * 4 + 2][r] = v.z; Ks[c4 * 4 + 3][r] = v.w;
        }
        if (tid < 64) Ms[tid] = mask[b * NK_ + k0 + tid];
        __syncthreads();

        ull acc2[4][2];
#pragma unroll
        for (int i = 0; i < 4; i++) { acc2[i][0] = 0ULL; acc2[i][1] = 0ULL; }

#pragma unroll
        for (int d = 0; d < 64; d++) {
            float4 aq = *(const float4*)&Qs[d][ty * 4];
            float4 bk = *(const float4*)&Ks[d][tx * 4];
            ull b20 = pack2(bk.x, bk.y);
            ull b21 = pack2(bk.z, bk.w);
            float aa[4] = { aq.x, aq.y, aq.z, aq.w };
#pragma unroll
            for (int i = 0; i < 4; i++) {
                ull ap = pack2(aa[i], aa[i]);
                acc2[i][0] = fma2(ap, b20, acc2[i][0]);
                acc2[i][1] = fma2(ap, b21, acc2[i][1]);
            }
        }

#pragma unroll
        for (int i = 0; i < 4; i++) {
            float2 f0 = unpack2(acc2[i][0]);
            float2 f1 = unpack2(acc2[i][1]);
            float s[4] = { f0.x, f0.y, f1.x, f1.y };
            size_t gaddr = ((size_t)((b * H_ + h) * NQ_ + q0 + ty * 4 + i)) * NK_ + k0 + tx * 4;
            float4 bv = *(const float4*)(bias + gaddr);
            float bb4[4] = { bv.x, bv.y, bv.z, bv.w };
            float e[4];
#pragma unroll
            for (int j = 0; j < 4; j++) {
                float sv = s[j] * 0.125f + bb4[j];
                e[j] = Ms[tx * 4 + j] ? 0.f : __expf(sv);
            }
            *(float4*)(scores + gaddr) = make_float4(e[0], e[1], e[2], e[3]);
            l_run[i] += (e[0] + e[1]) + (e[2] + e[3]);
        }
    }

#pragma unroll
    for (int i = 0; i < 4; i++) {
#pragma unroll
        for (int o = 1; o < 16; o <<= 1)
            l_run[i] += __shfl_xor_sync(0xffffffffu, l_run[i], o, 16);
        if (tx == 0)
            g_l[(b * H_ + h) * NQ_ + q0 + ty * 4 + i] = l_run[i];
    }
}

// ---------------- normalize + attn write + A@V + residual -------------------
__global__ __launch_bounds__(256) void av_kernel(
    const float* __restrict__ scores_in, const float* __restrict__ query,
    float* __restrict__ attn_out, float* __restrict__ out0)
{
    int b = blockIdx.z, h = blockIdx.y, q0 = blockIdx.x * 64;
    __shared__ float Ps[64][68];
    __shared__ float Vs[64][68];
    __shared__ float Li[64];

    int tid = threadIdx.x;
    int qid = tid >> 2, g = tid & 3;

    if (tid < 64) {
        int row = (b * H_ + h) * NQ_ + q0 + tid;
        Li[tid] = 1.0f / g_l[row];
    }

    ull acc2[8];
#pragma unroll
    for (int j = 0; j < 8; j++) acc2[j] = 0ULL;

    for (int k0 = 0; k0 < NK_; k0 += 64) {
        __syncthreads();
#pragma unroll
        for (int i = 0; i < 4; i++) {
            int idx = tid + i * 256;
            int r = idx >> 4, c4 = idx & 15;
            size_t gaddr = ((size_t)((b * H_ + h) * NQ_ + q0 + r)) * NK_ + k0 + c4 * 4;
            float4 e = *(const float4*)(scores_in + gaddr);
            float li = Li[r];
            float4 p = make_float4(e.x * li, e.y * li, e.z * li, e.w * li);
            *(float4*)(attn_out + gaddr) = p;
            *(float4*)&Ps[r][c4 * 4] = p;
        }
#pragma unroll
        for (int i = 0; i < 4; i++) {
            int idx = tid + i * 256;
            int r = idx >> 4, c4 = idx & 15;
            float4 v = *(const float4*)(g_kn + (size_t)(b * NK_ + k0 + r) * C_ + h * D_ + c4 * 4);
            *(float4*)&Vs[r][c4 * 4] = v;
        }
        __syncthreads();

#pragma unroll 8
        for (int kk = 0; kk < 64; kk++) {
            float pv = Ps[qid][kk];
            ull pp = pack2(pv, pv);
#pragma unroll
            for (int j = 0; j < 4; j++) {
                ull v0 = *(const ull*)&Vs[kk][16 * j + 4 * g];
                ull v1 = *(const ull*)&Vs[kk][16 * j + 4 * g + 2];
                acc2[2 * j]     = fma2(pp, v0, acc2[2 * j]);
                acc2[2 * j + 1] = fma2(pp, v1, acc2[2 * j + 1]);
            }
        }
    }

    if (out0) {
#pragma unroll
        for (int j = 0; j < 4; j++) {
            float2 f0 = unpack2(acc2[2 * j]);
            float2 f1 = unpack2(acc2[2 * j + 1]);
            size_t o = (size_t)(b * NQ_ + q0 + qid) * C_ + h * D_ + 16 * j + 4 * g;
            float4 qv = *(const float4*)(query + o);
            *(float4*)(out0 + o) = make_float4(qv.x + f0.x, qv.y + f0.y,
                                               qv.z + f1.x, qv.w + f1.y);
        }
    }
}

// ---------------- host ------------------------------------------------------
extern "C" void kernel_launch(void* const* d_in, const int* in_sizes, int n_in,
                              void* d_out, int out_size)
{
    const float* query  = (const float*)d_in[0];
    const float* memory = (const float*)d_in[1];
    const float* qpos   = (const float*)d_in[2];
    const float* mpos   = (const float*)d_in[3];
    const float* bias   = (const float*)d_in[4];
    const int*   mask   = (const int*)d_in[5];
    const float* Wk     = (const float*)d_in[6];
    const float* lnqw   = (const float*)d_in[7];
    const float* lnqb   = (const float*)d_in[8];
    const float* lnkw   = (const float*)d_in[9];
    const float* lnkb   = (const float*)d_in[10];
    (void)in_sizes; (void)n_in;

    float* out = (float*)d_out;
    const long long OUT0 = (long long)B_ * NQ_ * C_;
    const long long ATT  = (long long)B_ * H_ * NQ_ * NK_;

    float* out0 = nullptr;
    float* attn = nullptr;
    if ((long long)out_size >= OUT0 + ATT) { out0 = out; attn = out + OUT0; }
    else if ((long long)out_size >= ATT)   { attn = out; }
    else {
        out0 = out;
        cudaGetSymbolAddress((void**)&attn, g_scores);
    }

    float *gq_ptr, *gkn_ptr;
    __nv_bfloat16 *ahi, *alo, *bhi, *blo;
    cudaGetSymbolAddress((void**)&gq_ptr,  g_q);
    cudaGetSymbolAddress((void**)&gkn_ptr, g_kn);
    cudaGetSymbolAddress((void**)&ahi, g_ahi);
    cudaGetSymbolAddress((void**)&alo, g_alo);
    cudaGetSymbolAddress((void**)&bhi, g_bhi);
    cudaGetSymbolAddress((void**)&blo, g_blo);

    // 1) q = LN(query)+qpos ; 2) kn = LN(memory), split(kn+mpos)
    ln_kernel<<<B_ * NQ_, 256>>>(query, lnqw, lnqb, qpos, gq_ptr);
    ln_k_kernel<<<B_ * NK_, 256>>>(memory, lnkw, lnkb, mpos, gkn_ptr, ahi, alo);
    // 3) split Wk
    wconv_kernel<<<C_ * C_ / 1024, 256>>>(Wk, bhi, blo);
    // 4) K projection on tensor cores (mma.sync)
    {
        dim3 grid(C_ / 128, (B_ * NK_) / 128);
        kproj_mma<<<grid, 256>>>(ahi, alo, bhi, blo);
    }
    // 5) exp(scores) + row sums
    {
        dim3 grid(NQ_ / 64, H_, B_);
        qk_kernel<<<grid, 256>>>(bias, mask, attn);
    }
    // 6) normalize -> attn, A@V, residual
    {
        dim3 grid(NQ_ / 64, H_, B_);
        av_kernel<<<grid, 256>>>(attn, query, attn, out0);
    }
}

// round 6
// speedup vs baseline: 1.5901x; 1.2544x over previous
#include <cuda_runtime.h>
#include <cuda_bf16.h>
#include <cstdint>

typedef __nv_bfloat16  bf16;
typedef __nv_bfloat162 bf162;

#define B_  8
#define NQ_ 256
#define NK_ 4096
#define C_  1024
#define H_  16
#define D_  64

// ---------------- scratch (static device globals) ---------------------------
__device__ bf16 g_qhi[(size_t)B_ * NQ_ * C_];   // LN(q)+qpos hi
__device__ bf16 g_qlo[(size_t)B_ * NQ_ * C_];   // LN(q)+qpos lo
__device__ bf16 g_ahi[(size_t)B_ * NK_ * C_];   // (kn+mpos) hi
__device__ bf16 g_alo[(size_t)B_ * NK_ * C_];   // (kn+mpos) lo
__device__ bf16 g_vhi[(size_t)B_ * NK_ * C_];   // kn (=V) hi
__device__ bf16 g_vlo[(size_t)B_ * NK_ * C_];   // kn (=V) lo
__device__ bf16 g_khi[(size_t)B_ * NK_ * C_];   // K proj hi
__device__ bf16 g_klo[(size_t)B_ * NK_ * C_];   // K proj lo
__device__ bf16 g_bhi[C_ * C_];                 // Wk hi
__device__ bf16 g_blo[C_ * C_];                 // Wk lo
__device__ float g_l[B_ * H_ * NQ_];            // row sum-exp
__device__ float g_scores[(size_t)B_ * H_ * NQ_ * NK_]; // fallback

// ---------------- helpers ----------------------------------------------------
__device__ __forceinline__ uint32_t smem_u32(const void* p) {
    uint32_t a;
    asm("{ .reg .u64 t; cvta.to.shared.u64 t, %1; cvt.u32.u64 %0, t; }"
        : "=r"(a) : "l"(p));
    return a;
}
__device__ __forceinline__ void ldsm4(uint32_t* r, uint32_t addr) {
    asm volatile("ldmatrix.sync.aligned.m8n8.x4.shared.b16 {%0,%1,%2,%3}, [%4];"
                 : "=r"(r[0]), "=r"(r[1]), "=r"(r[2]), "=r"(r[3]) : "r"(addr));
}
__device__ __forceinline__ void ldsm4t(uint32_t* r, uint32_t addr) {
    asm volatile("ldmatrix.sync.aligned.m8n8.x4.trans.shared.b16 {%0,%1,%2,%3}, [%4];"
                 : "=r"(r[0]), "=r"(r[1]), "=r"(r[2]), "=r"(r[3]) : "r"(addr));
}
__device__ __forceinline__ void mma16816(float* d, const uint32_t* a,
                                         uint32_t b0, uint32_t b1) {
    asm volatile(
        "mma.sync.aligned.m16n8k16.row.col.f32.bf16.bf16.f32 "
        "{%0,%1,%2,%3}, {%4,%5,%6,%7}, {%8,%9}, {%0,%1,%2,%3};"
        : "+f"(d[0]), "+f"(d[1]), "+f"(d[2]), "+f"(d[3])
        : "r"(a[0]), "r"(a[1]), "r"(a[2]), "r"(a[3]), "r"(b0), "r"(b1));
}
__device__ __forceinline__ void cp16(uint32_t s, const void* g) {
    asm volatile("cp.async.cg.shared.global [%0], [%1], 16;"
                 :: "r"(s), "l"(__cvta_generic_to_global(g)));
}
__device__ __forceinline__ void split_bf16(float x, bf16& h, bf16& l) {
    h = __float2bfloat16(x);
    l = __float2bfloat16(x - __bfloat162float(h));
}

// ---------------- LayerNorm core ---------------------------------------------
__device__ __forceinline__ float4 ln_row(const float* x, const float* w,
                                         const float* bw, size_t base, int t,
                                         float* rs, float* rs2) {
    float4 v = *(const float4*)(x + base + t * 4);
    float s  = v.x + v.y + v.z + v.w;
    float s2 = v.x * v.x + v.y * v.y + v.z * v.z + v.w * v.w;
    int lane = t & 31, wid = t >> 5;
#pragma unroll
    for (int o = 16; o > 0; o >>= 1) {
        s  += __shfl_xor_sync(0xffffffffu, s,  o);
        s2 += __shfl_xor_sync(0xffffffffu, s2, o);
    }
    if (lane == 0) { rs[wid] = s; rs2[wid] = s2; }
    __syncthreads();
    if (t == 0) {
        float a = 0.f, b = 0.f;
#pragma unroll
        for (int i = 0; i < 8; i++) { a += rs[i]; b += rs2[i]; }
        rs[0] = a; rs2[0] = b;
    }
    __syncthreads();
    float mu  = rs[0]  * (1.0f / C_);
    float var = rs2[0] * (1.0f / C_) - mu * mu;
    float inv = rsqrtf(var + 1e-5f);
    float4 wv = *(const float4*)(w  + t * 4);
    float4 bv = *(const float4*)(bw + t * 4);
    float4 o;
    o.x = (v.x - mu) * inv * wv.x + bv.x;
    o.y = (v.y - mu) * inv * wv.y + bv.y;
    o.z = (v.z - mu) * inv * wv.z + bv.z;
    o.w = (v.w - mu) * inv * wv.w + bv.w;
    return o;
}

// query: LN + qpos -> hi/lo
__global__ __launch_bounds__(256) void ln_q_kernel(
    const float* __restrict__ x, const float* __restrict__ w,
    const float* __restrict__ bw, const float* __restrict__ pos,
    bf16* __restrict__ qhi, bf16* __restrict__ qlo)
{
    __shared__ float rs[8], rs2[8];
    int row = blockIdx.x, t = threadIdx.x;
    size_t base = (size_t)row * C_;
    float4 o = ln_row(x, w, bw, base, t, rs, rs2);
    float4 p = *(const float4*)(pos + base + t * 4);
    float a0 = o.x + p.x, a1 = o.y + p.y, a2 = o.z + p.z, a3 = o.w + p.w;
    bf16 h0, h1, h2, h3, l0, l1, l2, l3;
    split_bf16(a0, h0, l0); split_bf16(a1, h1, l1);
    split_bf16(a2, h2, l2); split_bf16(a3, h3, l3);
    *(bf162*)(qhi + base + t * 4)     = bf162(h0, h1);
    *(bf162*)(qhi + base + t * 4 + 2) = bf162(h2, h3);
    *(bf162*)(qlo + base + t * 4)     = bf162(l0, l1);
    *(bf162*)(qlo + base + t * 4 + 2) = bf162(l2, l3);
}

// memory: LN -> V hi/lo ; LN+mpos -> A hi/lo
__global__ __launch_bounds__(256) void ln_k_kernel(
    const float* __restrict__ x, const float* __restrict__ w,
    const float* __restrict__ bw, const float* __restrict__ pos,
    bf16* __restrict__ vhi, bf16* __restrict__ vlo,
    bf16* __restrict__ ahi, bf16* __restrict__ alo)
{
    __shared__ float rs[8], rs2[8];
    int row = blockIdx.x, t = threadIdx.x;
    size_t base = (size_t)row * C_;
    float4 o = ln_row(x, w, bw, base, t, rs, rs2);

    bf16 h0, h1, h2, h3, l0, l1, l2, l3;
    split_bf16(o.x, h0, l0); split_bf16(o.y, h1, l1);
    split_bf16(o.z, h2, l2); split_bf16(o.w, h3, l3);
    *(bf162*)(vhi + base + t * 4)     = bf162(h0, h1);
    *(bf162*)(vhi + base + t * 4 + 2) = bf162(h2, h3);
    *(bf162*)(vlo + base + t * 4)     = bf162(l0, l1);
    *(bf162*)(vlo + base + t * 4 + 2) = bf162(l2, l3);

    float4 p = *(const float4*)(pos + base + t * 4);
    float a0 = o.x + p.x, a1 = o.y + p.y, a2 = o.z + p.z, a3 = o.w + p.w;
    split_bf16(a0, h0, l0); split_bf16(a1, h1, l1);
    split_bf16(a2, h2, l2); split_bf16(a3, h3, l3);
    *(bf162*)(ahi + base + t * 4)     = bf162(h0, h1);
    *(bf162*)(ahi + base + t * 4 + 2) = bf162(h2, h3);
    *(bf162*)(alo + base + t * 4)     = bf162(l0, l1);
    *(bf162*)(alo + base + t * 4 + 2) = bf162(l2, l3);
}

// Wk split
__global__ __launch_bounds__(256) void wconv_kernel(
    const float* __restrict__ Wk, bf16* __restrict__ hi, bf16* __restrict__ lo)
{
    size_t i = (size_t)blockIdx.x * 1024 + threadIdx.x * 4;
    float4 v = *(const float4*)(Wk + i);
    bf16 h0, h1, h2, h3, l0, l1, l2, l3;
    split_bf16(v.x, h0, l0); split_bf16(v.y, h1, l1);
    split_bf16(v.z, h2, l2); split_bf16(v.w, h3, l3);
    *(bf162*)(hi + i)     = bf162(h0, h1);
    *(bf162*)(hi + i + 2) = bf162(h2, h3);
    *(bf162*)(lo + i)     = bf162(l0, l1);
    *(bf162*)(lo + i + 2) = bf162(l2, l3);
}

// ---------------- K projection: mma.sync, cp.async double-buffered ----------
// K[m][n] = sum_k A[m][k] * Wk[n][k]; M=32768, N=1024, K=1024
// block 128x128, 8 warps (4x2), warp 32x64, K-chunk 32, 2 stages
#define KP_AH 0
#define KP_AL 10240
#define KP_BH 20480
#define KP_BL 30720
#define KP_STAGE 40960
#define KP_SMEM (2 * KP_STAGE)

__global__ __launch_bounds__(256) void kproj_mma(
    const bf16* __restrict__ ahi_g, const bf16* __restrict__ alo_g,
    const bf16* __restrict__ bhi_g, const bf16* __restrict__ blo_g,
    bf16* __restrict__ khi_g, bf16* __restrict__ klo_g)
{
    extern __shared__ char sm[];
    uint32_t smb = smem_u32(sm);
    int tid = threadIdx.x, lane = tid & 31, wid = tid >> 5;
    int wm = wid >> 1, wn = wid & 1;
    int m0 = blockIdx.y * 128, n0 = blockIdx.x * 128;

    float acc[2][8][4];
#pragma unroll
    for (int mt = 0; mt < 2; mt++)
#pragma unroll
        for (int nt = 0; nt < 8; nt++)
#pragma unroll
            for (int e = 0; e < 4; e++) acc[mt][nt][e] = 0.f;

    int a_r = lane & 15, a_c = (lane >> 4) << 3;
    int b_r = (lane & 7) + ((lane >> 4) << 3), b_c = ((lane >> 3) & 1) << 3;

    auto issue = [&](int s, int kc) {
#pragma unroll
        for (int i = 0; i < 2; i++) {
            int idx = tid + i * 256;                 // 0..511
            int r = idx >> 2, c = (idx & 3) << 3;
            uint32_t so = (uint32_t)(r * 40 + c) * 2;
            uint32_t sb = smb + s * KP_STAGE;
            size_t ga = (size_t)(m0 + r) * C_ + kc * 32 + c;
            size_t gb = (size_t)(n0 + r) * C_ + kc * 32 + c;
            cp16(sb + KP_AH + so, ahi_g + ga);
            cp16(sb + KP_AL + so, alo_g + ga);
            cp16(sb + KP_BH + so, bhi_g + gb);
            cp16(sb + KP_BL + so, blo_g + gb);
        }
    };

    issue(0, 0);
    asm volatile("cp.async.commit_group;");

    for (int kc = 0; kc < 32; kc++) {
        int cur = kc & 1;
        if (kc + 1 < 32) {
            issue(cur ^ 1, kc + 1);
            asm volatile("cp.async.commit_group;");
            asm volatile("cp.async.wait_group 1;");
        } else {
            asm volatile("cp.async.wait_group 0;");
        }
        __syncthreads();

        uint32_t base = smb + cur * KP_STAGE;
#pragma unroll
        for (int ks = 0; ks < 2; ks++) {
            int k0 = ks * 16;
            uint32_t Ah[2][4], Al[2][4], Bf[4][4];
#pragma unroll
            for (int mt = 0; mt < 2; mt++) {
                ldsm4(Ah[mt], base + KP_AH + ((wm * 32 + mt * 16 + a_r) * 40 + k0 + a_c) * 2);
                ldsm4(Al[mt], base + KP_AL + ((wm * 32 + mt * 16 + a_r) * 40 + k0 + a_c) * 2);
            }
#pragma unroll
            for (int p = 0; p < 4; p++)
                ldsm4(Bf[p], base + KP_BH + ((wn * 64 + p * 16 + b_r) * 40 + k0 + b_c) * 2);
#pragma unroll
            for (int mt = 0; mt < 2; mt++)
#pragma unroll
                for (int p = 0; p < 4; p++) {
                    mma16816(acc[mt][2 * p],     Ah[mt], Bf[p][0], Bf[p][1]);
                    mma16816(acc[mt][2 * p + 1], Ah[mt], Bf[p][2], Bf[p][3]);
                    mma16816(acc[mt][2 * p],     Al[mt], Bf[p][0], Bf[p][1]);
                    mma16816(acc[mt][2 * p + 1], Al[mt], Bf[p][2], Bf[p][3]);
                }
#pragma unroll
            for (int p = 0; p < 4; p++)
                ldsm4(Bf[p], base + KP_BL + ((wn * 64 + p * 16 + b_r) * 40 + k0 + b_c) * 2);
#pragma unroll
            for (int mt = 0; mt < 2; mt++)
#pragma unroll
                for (int p = 0; p < 4; p++) {
                    mma16816(acc[mt][2 * p],     Ah[mt], Bf[p][0], Bf[p][1]);
                    mma16816(acc[mt][2 * p + 1], Ah[mt], Bf[p][2], Bf[p][3]);
                }
        }
        __syncthreads();
    }

    int gid = lane >> 2, lid2 = (lane & 3) * 2;
#pragma unroll
    for (int mt = 0; mt < 2; mt++)
#pragma unroll
        for (int nt = 0; nt < 8; nt++) {
            int row = m0 + wm * 32 + mt * 16 + gid;
            int col = n0 + wn * 64 + nt * 8 + lid2;
            bf16 h0, h1, h2, h3, l0, l1, l2, l3;
            split_bf16(acc[mt][nt][0], h0, l0);
            split_bf16(acc[mt][nt][1], h1, l1);
            split_bf16(acc[mt][nt][2], h2, l2);
            split_bf16(acc[mt][nt][3], h3, l3);
            *(bf162*)(khi_g + (size_t)row * C_ + col)       = bf162(h0, h1);
            *(bf162*)(klo_g + (size_t)row * C_ + col)       = bf162(l0, l1);
            *(bf162*)(khi_g + (size_t)(row + 8) * C_ + col) = bf162(h2, h3);
            *(bf162*)(klo_g + (size_t)(row + 8) * C_ + col) = bf162(l2, l3);
        }
}

// ---------------- QK^T (tensor) + bias + mask -> e = exp(s), row sums -------
// grid (4, 16, 8), 256 thr, warps 2(q) x 4(k), warp tile 32q x 32k, k-chunk 128
#define QKS_QH 0
#define QKS_QL 9216
#define QKS_KH 18432
#define QKS_KL 36864
#define QKS_MS 55296
#define QKS_LS 55808
#define QKS_SMEM 56064

__global__ __launch_bounds__(256) void qk_tc(
    const bf16* __restrict__ qhi, const bf16* __restrict__ qlo,
    const bf16* __restrict__ khi, const bf16* __restrict__ klo,
    const float* __restrict__ bias, const int* __restrict__ mask,
    float* __restrict__ scores)
{
    extern __shared__ char sm[];
    uint32_t smb = smem_u32(sm);
    int b = blockIdx.z, h = blockIdx.y, q0 = blockIdx.x * 64;
    int tid = threadIdx.x, lane = tid & 31, wid = tid >> 5;
    int wm = wid >> 2, wn = wid & 3;
    int* Ms = (int*)(sm + QKS_MS);
    float* lsum = (float*)(sm + QKS_LS);
    if (tid < 64) lsum[tid] = 0.f;

#pragma unroll
    for (int i = 0; i < 2; i++) {
        int idx = tid + i * 256;
        int r = idx >> 3, c = (idx & 7) << 3;
        size_t g = (size_t)(b * NQ_ + q0 + r) * C_ + h * D_ + c;
        *(uint4*)(sm + QKS_QH + (r * 72 + c) * 2) = *(const uint4*)(qhi + g);
        *(uint4*)(sm + QKS_QL + (r * 72 + c) * 2) = *(const uint4*)(qlo + g);
    }
    __syncthreads();

    int a_r = lane & 15, a_c = (lane >> 4) << 3;
    int b_r = (lane & 7) + ((lane >> 4) << 3), b_c = ((lane >> 3) & 1) << 3;
    int gid = lane >> 2, lid2 = (lane & 3) * 2;

    uint32_t Qh[2][4][4], Ql[2][4][4];
#pragma unroll
    for (int mt = 0; mt < 2; mt++)
#pragma unroll
        for (int ks = 0; ks < 4; ks++) {
            ldsm4(Qh[mt][ks], smb + QKS_QH + ((wm * 32 + mt * 16 + a_r) * 72 + ks * 16 + a_c) * 2);
            ldsm4(Ql[mt][ks], smb + QKS_QL + ((wm * 32 + mt * 16 + a_r) * 72 + ks * 16 + a_c) * 2);
        }

    float rsum[2][2] = { {0.f, 0.f}, {0.f, 0.f} };

    for (int k0 = 0; k0 < NK_; k0 += 128) {
        __syncthreads();
#pragma unroll
        for (int i = 0; i < 4; i++) {
            int idx = tid + i * 256;
            int r = idx >> 3, c = (idx & 7) << 3;
            size_t g = (size_t)(b * NK_ + k0 + r) * C_ + h * D_ + c;
            *(uint4*)(sm + QKS_KH + (r * 72 + c) * 2) = *(const uint4*)(khi + g);
            *(uint4*)(sm + QKS_KL + (r * 72 + c) * 2) = *(const uint4*)(klo + g);
        }
        if (tid < 128) Ms[tid] = mask[b * NK_ + k0 + tid];
        __syncthreads();

        float acc[2][4][4];
#pragma unroll
        for (int mt = 0; mt < 2; mt++)
#pragma unroll
            for (int nf = 0; nf < 4; nf++)
#pragma unroll
                for (int e = 0; e < 4; e++) acc[mt][nf][e] = 0.f;

#pragma unroll
        for (int ks = 0; ks < 4; ks++) {
            uint32_t Bh[2][4], Bl[2][4];
#pragma unroll
            for (int np = 0; np < 2; np++) {
                ldsm4(Bh[np], smb + QKS_KH + ((wn * 32 + np * 16 + b_r) * 72 + ks * 16 + b_c) * 2);
                ldsm4(Bl[np], smb + QKS_KL + ((wn * 32 + np * 16 + b_r) * 72 + ks * 16 + b_c) * 2);
            }
#pragma unroll
            for (int mt = 0; mt < 2; mt++)
#pragma unroll
                for (int np = 0; np < 2; np++) {
                    mma16816(acc[mt][2 * np],     Qh[mt][ks], Bh[np][0], Bh[np][1]);
                    mma16816(acc[mt][2 * np + 1], Qh[mt][ks], Bh[np][2], Bh[np][3]);
                    mma16816(acc[mt][2 * np],     Ql[mt][ks], Bh[np][0], Bh[np][1]);
                    mma16816(acc[mt][2 * np + 1], Ql[mt][ks], Bh[np][2], Bh[np][3]);
                    mma16816(acc[mt][2 * np],     Qh[mt][ks], Bl[np][0], Bl[np][1]);
                    mma16816(acc[mt][2 * np + 1], Qh[mt][ks], Bl[np][2], Bl[np][3]);
                }
        }

#pragma unroll
        for (int mt = 0; mt < 2; mt++)
#pragma unroll
            for (int nf = 0; nf < 4; nf++) {
                int cl = wn * 32 + nf * 8 + lid2;
                int col = k0 + cl;
                int msk0 = Ms[cl], msk1 = Ms[cl + 1];
                size_t row0 = ((size_t)((b * H_ + h) * NQ_) + q0 + wm * 32 + mt * 16 + gid) * NK_;
                size_t row1 = row0 + (size_t)8 * NK_;
                float2 bv0 = *(const float2*)(bias + row0 + col);
                float2 bv1 = *(const float2*)(bias + row1 + col);
                float e00 = msk0 ? 0.f : __expf(acc[mt][nf][0] * 0.125f + bv0.x);
                float e01 = msk1 ? 0.f : __expf(acc[mt][nf][1] * 0.125f + bv0.y);
                float e10 = msk0 ? 0.f : __expf(acc[mt][nf][2] * 0.125f + bv1.x);
                float e11 = msk1 ? 0.f : __expf(acc[mt][nf][3] * 0.125f + bv1.y);
                *(float2*)(scores + row0 + col) = make_float2(e00, e01);
                *(float2*)(scores + row1 + col) = make_float2(e10, e11);
                rsum[mt][0] += e00 + e01;
                rsum[mt][1] += e10 + e11;
            }
    }

#pragma unroll
    for (int mt = 0; mt < 2; mt++)
#pragma unroll
        for (int rr = 0; rr < 2; rr++) {
            float v = rsum[mt][rr];
            v += __shfl_xor_sync(0xffffffffu, v, 1);
            v += __shfl_xor_sync(0xffffffffu, v, 2);
            if ((lane & 3) == 0)
                atomicAdd(&lsum[wm * 32 + mt * 16 + gid + rr * 8], v);
        }
    __syncthreads();
    if (tid < 64)
        g_l[(b * H_ + h) * NQ_ + q0 + tid] = lsum[tid];
}

// ---------------- A@V (tensor) + normalize + attn write + residual ----------
// grid (4, 16, 8), 256 thr, warps 2(q) x 4(d), warp tile 32q x 16d, k-chunk 128
#define AVS_PH 0
#define AVS_PL 17408
#define AVS_VH 34816
#define AVS_VL 53248
#define AVS_LI 71680
#define AVS_SMEM 71936

__global__ __launch_bounds__(256) void av_tc(
    const float* __restrict__ scores_in,
    const bf16* __restrict__ vhi, const bf16* __restrict__ vlo,
    const float* __restrict__ query,
    float* __restrict__ attn_out, float* __restrict__ out0)
{
    extern __shared__ char sm[];
    uint32_t smb = smem_u32(sm);
    int b = blockIdx.z, h = blockIdx.y, q0 = blockIdx.x * 64;
    int tid = threadIdx.x, lane = tid & 31, wid = tid >> 5;
    int wm = wid >> 2, wn = wid & 3;
    float* Li = (float*)(sm + AVS_LI);
    if (tid < 64)
        Li[tid] = 1.0f / g_l[(b * H_ + h) * NQ_ + q0 + tid];

    float acc[2][2][4];
#pragma unroll
    for (int mt = 0; mt < 2; mt++)
#pragma unroll
        for (int nf = 0; nf < 2; nf++)
#pragma unroll
            for (int e = 0; e < 4; e++) acc[mt][nf][e] = 0.f;

    int a_r = lane & 15, a_c = (lane >> 4) << 3;
    int v_r = (lane & 7) + (((lane >> 3) & 1) << 3), v_c = (lane >> 4) << 3;

    for (int k0 = 0; k0 < NK_; k0 += 128) {
        __syncthreads();
        // e -> normalize -> attn + P hi/lo smem
#pragma unroll
        for (int i = 0; i < 8; i++) {
            int idx = tid + i * 256;                  // 0..2047
            int r = idx >> 5, cq = (idx & 31) * 4;
            size_t ga = ((size_t)((b * H_ + h) * NQ_) + q0 + r) * NK_ + k0 + cq;
            float4 e = *(const float4*)(scores_in + ga);
            float li = Li[r];
            float4 p = make_float4(e.x * li, e.y * li, e.z * li, e.w * li);
            *(float4*)(attn_out + ga) = p;
            bf16 h0, h1, h2, h3, l0, l1, l2, l3;
            split_bf16(p.x, h0, l0); split_bf16(p.y, h1, l1);
            split_bf16(p.z, h2, l2); split_bf16(p.w, h3, l3);
            uint32_t so = (uint32_t)(r * 136 + cq) * 2;
            *(bf162*)(sm + AVS_PH + so)     = bf162(h0, h1);
            *(bf162*)(sm + AVS_PH + so + 4) = bf162(h2, h3);
            *(bf162*)(sm + AVS_PL + so)     = bf162(l0, l1);
            *(bf162*)(sm + AVS_PL + so + 4) = bf162(l2, l3);
        }
        // V tiles
#pragma unroll
        for (int i = 0; i < 4; i++) {
            int idx = tid + i * 256;
            int r = idx >> 3, c = (idx & 7) << 3;
            size_t g = (size_t)(b * NK_ + k0 + r) * C_ + h * D_ + c;
            *(uint4*)(sm + AVS_VH + (r * 72 + c) * 2) = *(const uint4*)(vhi + g);
            *(uint4*)(sm + AVS_VL + (r * 72 + c) * 2) = *(const uint4*)(vlo + g);
        }
        __syncthreads();

#pragma unroll
        for (int ks = 0; ks < 8; ks++) {
            uint32_t Pf[2][4], Pl[2][4], Bh[4], Bl[4];
#pragma unroll
            for (int mt = 0; mt < 2; mt++) {
                ldsm4(Pf[mt], smb + AVS_PH + ((wm * 32 + mt * 16 + a_r) * 136 + ks * 16 + a_c) * 2);
                ldsm4(Pl[mt], smb + AVS_PL + ((wm * 32 + mt * 16 + a_r) * 136 + ks * 16 + a_c) * 2);
            }
            ldsm4t(Bh, smb + AVS_VH + ((ks * 16 + v_r) * 72 + wn * 16 + v_c) * 2);
            ldsm4t(Bl, smb + AVS_VL + ((ks * 16 + v_r) * 72 + wn * 16 + v_c) * 2);
#pragma unroll
            for (int mt = 0; mt < 2; mt++)
#pragma unroll
                for (int nf = 0; nf < 2; nf++) {
                    mma16816(acc[mt][nf], Pf[mt], Bh[nf * 2], Bh[nf * 2 + 1]);
                    mma16816(acc[mt][nf], Pl[mt], Bh[nf * 2], Bh[nf * 2 + 1]);
                    mma16816(acc[mt][nf], Pf[mt], Bl[nf * 2], Bl[nf * 2 + 1]);
                }
        }
    }

    if (out0) {
        int gid = lane >> 2, lid2 = (lane & 3) * 2;
#pragma unroll
        for (int mt = 0; mt < 2; mt++)
#pragma unroll
            for (int nf = 0; nf < 2; nf++) {
                int row = b * NQ_ + q0 + wm * 32 + mt * 16 + gid;
                int col = h * D_ + wn * 16 + nf * 8 + lid2;
                float2 qv0 = *(const float2*)(query + (size_t)row * C_ + col);
                float2 qv1 = *(const float2*)(query + (size_t)(row + 8) * C_ + col);
                *(float2*)(out0 + (size_t)row * C_ + col) =
                    make_float2(qv0.x + acc[mt][nf][0], qv0.y + acc[mt][nf][1]);
                *(float2*)(out0 + (size_t)(row + 8) * C_ + col) =
                    make_float2(qv1.x + acc[mt][nf][2], qv1.y + acc[mt][nf][3]);
            }
    }
}

// ---------------- host ------------------------------------------------------
extern "C" void kernel_launch(void* const* d_in, const int* in_sizes, int n_in,
                              void* d_out, int out_size)
{
    const float* query  = (const float*)d_in[0];
    const float* memory = (const float*)d_in[1];
    const float* qpos   = (const float*)d_in[2];
    const float* mpos   = (const float*)d_in[3];
    const float* bias   = (const float*)d_in[4];
    const int*   mask   = (const int*)d_in[5];
    const float* Wk     = (const float*)d_in[6];
    const float* lnqw   = (const float*)d_in[7];
    const float* lnqb   = (const float*)d_in[8];
    const float* lnkw   = (const float*)d_in[9];
    const float* lnkb   = (const float*)d_in[10];
    (void)in_sizes; (void)n_in;

    float* out = (float*)d_out;
    const long long OUT0 = (long long)B_ * NQ_ * C_;
    const long long ATT  = (long long)B_ * H_ * NQ_ * NK_;

    float* out0 = nullptr;
    float* attn = nullptr;
    if ((long long)out_size >= OUT0 + ATT) { out0 = out; attn = out + OUT0; }
    else if ((long long)out_size >= ATT)   { attn = out; }
    else {
        out0 = out;
        cudaGetSymbolAddress((void**)&attn, g_scores);
    }

    bf16 *qhi, *qlo, *ahi, *alo, *vhi, *vlo, *khi, *klo, *bhi, *blo;
    cudaGetSymbolAddress((void**)&qhi, g_qhi);
    cudaGetSymbolAddress((void**)&qlo, g_qlo);
    cudaGetSymbolAddress((void**)&ahi, g_ahi);
    cudaGetSymbolAddress((void**)&alo, g_alo);
    cudaGetSymbolAddress((void**)&vhi, g_vhi);
    cudaGetSymbolAddress((void**)&vlo, g_vlo);
    cudaGetSymbolAddress((void**)&khi, g_khi);
    cudaGetSymbolAddress((void**)&klo, g_klo);
    cudaGetSymbolAddress((void**)&bhi, g_bhi);
    cudaGetSymbolAddress((void**)&blo, g_blo);

    cudaFuncSetAttribute(kproj_mma, cudaFuncAttributeMaxDynamicSharedMemorySize, KP_SMEM);
    cudaFuncSetAttribute(qk_tc,     cudaFuncAttributeMaxDynamicSharedMemorySize, QKS_SMEM);
    cudaFuncSetAttribute(av_tc,     cudaFuncAttributeMaxDynamicSharedMemorySize, AVS_SMEM);

    ln_q_kernel<<<B_ * NQ_, 256>>>(query, lnqw, lnqb, qpos, qhi, qlo);
    ln_k_kernel<<<B_ * NK_, 256>>>(memory, lnkw, lnkb, mpos, vhi, vlo, ahi, alo);
    wconv_kernel<<<C_ * C_ / 1024, 256>>>(Wk, bhi, blo);
    {
        dim3 grid(C_ / 128, (B_ * NK_) / 128);
        kproj_mma<<<grid, 256, KP_SMEM>>>(ahi, alo, bhi, blo, khi, klo);
    }
    {
        dim3 grid(NQ_ / 64, H_, B_);
        qk_tc<<<grid, 256, QKS_SMEM>>>(qhi, qlo, khi, klo, bias, mask, attn);
    }
    {
        dim3 grid(NQ_ / 64, H_, B_);
        av_tc<<<grid, 256, AVS_SMEM>>>(attn, vhi, vlo, query, attn, out0);
    }
}

// round 7
// speedup vs baseline: 2.4244x; 1.5247x over previous
#include <cuda_runtime.h>
#include <cuda_bf16.h>
#include <cstdint>

typedef __nv_bfloat16  bf16;
typedef __nv_bfloat162 bf162;
typedef unsigned long long ull;

#define B_  8
#define NQ_ 256
#define NK_ 4096
#define C_  1024
#define H_  16
#define D_  64

// ---------------- scratch (static device globals) ---------------------------
__device__ bf16 g_qhi[(size_t)B_ * NQ_ * C_];
__device__ bf16 g_qlo[(size_t)B_ * NQ_ * C_];
__device__ bf16 g_ahi[(size_t)B_ * NK_ * C_];
__device__ bf16 g_alo[(size_t)B_ * NK_ * C_];
__device__ bf16 g_vhi[(size_t)B_ * NK_ * C_];
__device__ bf16 g_vlo[(size_t)B_ * NK_ * C_];
__device__ bf16 g_khi[(size_t)B_ * NK_ * C_];
__device__ bf16 g_klo[(size_t)B_ * NK_ * C_];
__device__ bf16 g_bhi[C_ * C_];
__device__ bf16 g_blo[C_ * C_];
__device__ float g_l[B_ * H_ * NQ_];
__device__ float g_scores[(size_t)B_ * H_ * NQ_ * NK_];

// ---------------- helpers ----------------------------------------------------
__device__ __forceinline__ uint32_t smem_u32(const void* p) {
    uint32_t a;
    asm("{ .reg .u64 t; cvta.to.shared.u64 t, %1; cvt.u32.u64 %0, t; }"
        : "=r"(a) : "l"(p));
    return a;
}
__device__ __forceinline__ void ldsm4(uint32_t* r, uint32_t addr) {
    asm volatile("ldmatrix.sync.aligned.m8n8.x4.shared.b16 {%0,%1,%2,%3}, [%4];"
                 : "=r"(r[0]), "=r"(r[1]), "=r"(r[2]), "=r"(r[3]) : "r"(addr));
}
__device__ __forceinline__ void ldsm4t(uint32_t* r, uint32_t addr) {
    asm volatile("ldmatrix.sync.aligned.m8n8.x4.trans.shared.b16 {%0,%1,%2,%3}, [%4];"
                 : "=r"(r[0]), "=r"(r[1]), "=r"(r[2]), "=r"(r[3]) : "r"(addr));
}
__device__ __forceinline__ void mma16816(float* d, const uint32_t* a,
                                         uint32_t b0, uint32_t b1) {
    asm volatile(
        "mma.sync.aligned.m16n8k16.row.col.f32.bf16.bf16.f32 "
        "{%0,%1,%2,%3}, {%4,%5,%6,%7}, {%8,%9}, {%0,%1,%2,%3};"
        : "+f"(d[0]), "+f"(d[1]), "+f"(d[2]), "+f"(d[3])
        : "r"(a[0]), "r"(a[1]), "r"(a[2]), "r"(a[3]), "r"(b0), "r"(b1));
}
__device__ __forceinline__ void cp16(uint32_t s, const void* g) {
    asm volatile("cp.async.cg.shared.global [%0], [%1], 16;"
                 :: "r"(s), "l"(__cvta_generic_to_global(g)));
}
__device__ __forceinline__ void split_bf16(float x, bf16& h, bf16& l) {
    h = __float2bfloat16(x);
    l = __float2bfloat16(x - __bfloat162float(h));
}
// packed f32x2
__device__ __forceinline__ ull pack2(float x, float y) {
    ull r;
    asm("mov.b64 %0, {%1, %2};" : "=l"(r)
        : "r"(__float_as_uint(x)), "r"(__float_as_uint(y)));
    return r;
}
__device__ __forceinline__ float2 unpack2(ull v) {
    unsigned lo, hi;
    asm("mov.b64 {%0, %1}, %2;" : "=r"(lo), "=r"(hi) : "l"(v));
    return make_float2(__uint_as_float(lo), __uint_as_float(hi));
}
__device__ __forceinline__ ull fma2(ull a, ull b, ull c) {
    ull d;
    asm("fma.rn.f32x2 %0, %1, %2, %3;" : "=l"(d) : "l"(a), "l"(b), "l"(c));
    return d;
}
__device__ __forceinline__ ull add2(ull a, ull b) {
    ull d;
    asm("add.rn.f32x2 %0, %1, %2;" : "=l"(d) : "l"(a), "l"(b));
    return d;
}

// ---------------- LayerNorm core ---------------------------------------------
__device__ __forceinline__ float4 ln_row(const float* x, const float* w,
                                         const float* bw, size_t base, int t,
                                         float* rs, float* rs2) {
    float4 v = *(const float4*)(x + base + t * 4);
    float s  = v.x + v.y + v.z + v.w;
    float s2 = v.x * v.x + v.y * v.y + v.z * v.z + v.w * v.w;
    int lane = t & 31, wid = t >> 5;
#pragma unroll
    for (int o = 16; o > 0; o >>= 1) {
        s  += __shfl_xor_sync(0xffffffffu, s,  o);
        s2 += __shfl_xor_sync(0xffffffffu, s2, o);
    }
    if (lane == 0) { rs[wid] = s; rs2[wid] = s2; }
    __syncthreads();
    if (t == 0) {
        float a = 0.f, b = 0.f;
#pragma unroll
        for (int i = 0; i < 8; i++) { a += rs[i]; b += rs2[i]; }
        rs[0] = a; rs2[0] = b;
    }
    __syncthreads();
    float mu  = rs[0]  * (1.0f / C_);
    float var = rs2[0] * (1.0f / C_) - mu * mu;
    float inv = rsqrtf(var + 1e-5f);
    float4 wv = *(const float4*)(w  + t * 4);
    float4 bv = *(const float4*)(bw + t * 4);
    float4 o;
    o.x = (v.x - mu) * inv * wv.x + bv.x;
    o.y = (v.y - mu) * inv * wv.y + bv.y;
    o.z = (v.z - mu) * inv * wv.z + bv.z;
    o.w = (v.w - mu) * inv * wv.w + bv.w;
    return o;
}

__global__ __launch_bounds__(256) void ln_q_kernel(
    const float* __restrict__ x, const float* __restrict__ w,
    const float* __restrict__ bw, const float* __restrict__ pos,
    bf16* __restrict__ qhi, bf16* __restrict__ qlo)
{
    __shared__ float rs[8], rs2[8];
    int row = blockIdx.x, t = threadIdx.x;
    size_t base = (size_t)row * C_;
    float4 o = ln_row(x, w, bw, base, t, rs, rs2);
    float4 p = *(const float4*)(pos + base + t * 4);
    float a0 = o.x + p.x, a1 = o.y + p.y, a2 = o.z + p.z, a3 = o.w + p.w;
    bf16 h0, h1, h2, h3, l0, l1, l2, l3;
    split_bf16(a0, h0, l0); split_bf16(a1, h1, l1);
    split_bf16(a2, h2, l2); split_bf16(a3, h3, l3);
    *(bf162*)(qhi + base + t * 4)     = bf162(h0, h1);
    *(bf162*)(qhi + base + t * 4 + 2) = bf162(h2, h3);
    *(bf162*)(qlo + base + t * 4)     = bf162(l0, l1);
    *(bf162*)(qlo + base + t * 4 + 2) = bf162(l2, l3);
}

__global__ __launch_bounds__(256) void ln_k_kernel(
    const float* __restrict__ x, const float* __restrict__ w,
    const float* __restrict__ bw, const float* __restrict__ pos,
    bf16* __restrict__ vhi, bf16* __restrict__ vlo,
    bf16* __restrict__ ahi, bf16* __restrict__ alo)
{
    __shared__ float rs[8], rs2[8];
    int row = blockIdx.x, t = threadIdx.x;
    size_t base = (size_t)row * C_;
    float4 o = ln_row(x, w, bw, base, t, rs, rs2);

    bf16 h0, h1, h2, h3, l0, l1, l2, l3;
    split_bf16(o.x, h0, l0); split_bf16(o.y, h1, l1);
    split_bf16(o.z, h2, l2); split_bf16(o.w, h3, l3);
    *(bf162*)(vhi + base + t * 4)     = bf162(h0, h1);
    *(bf162*)(vhi + base + t * 4 + 2) = bf162(h2, h3);
    *(bf162*)(vlo + base + t * 4)     = bf162(l0, l1);
    *(bf162*)(vlo + base + t * 4 + 2) = bf162(l2, l3);

    float4 p = *(const float4*)(pos + base + t * 4);
    float a0 = o.x + p.x, a1 = o.y + p.y, a2 = o.z + p.z, a3 = o.w + p.w;
    split_bf16(a0, h0, l0); split_bf16(a1, h1, l1);
    split_bf16(a2, h2, l2); split_bf16(a3, h3, l3);
    *(bf162*)(ahi + base + t * 4)     = bf162(h0, h1);
    *(bf162*)(ahi + base + t * 4 + 2) = bf162(h2, h3);
    *(bf162*)(alo + base + t * 4)     = bf162(l0, l1);
    *(bf162*)(alo + base + t * 4 + 2) = bf162(l2, l3);
}

__global__ __launch_bounds__(256) void wconv_kernel(
    const float* __restrict__ Wk, bf16* __restrict__ hi, bf16* __restrict__ lo)
{
    size_t i = (size_t)blockIdx.x * 1024 + threadIdx.x * 4;
    float4 v = *(const float4*)(Wk + i);
    bf16 h0, h1, h2, h3, l0, l1, l2, l3;
    split_bf16(v.x, h0, l0); split_bf16(v.y, h1, l1);
    split_bf16(v.z, h2, l2); split_bf16(v.w, h3, l3);
    *(bf162*)(hi + i)     = bf162(h0, h1);
    *(bf162*)(hi + i + 2) = bf162(h2, h3);
    *(bf162*)(lo + i)     = bf162(l0, l1);
    *(bf162*)(lo + i + 2) = bf162(l2, l3);
}

// ---------------- K projection: mma.sync, cp.async 2-stage, 2 CTA/SM --------
#define KP_AH 0
#define KP_AL 10240
#define KP_BH 20480
#define KP_BL 30720
#define KP_STAGE 40960
#define KP_SMEM (2 * KP_STAGE)

__global__ __launch_bounds__(256, 2) void kproj_mma(
    const bf16* __restrict__ ahi_g, const bf16* __restrict__ alo_g,
    const bf16* __restrict__ bhi_g, const bf16* __restrict__ blo_g,
    bf16* __restrict__ khi_g, bf16* __restrict__ klo_g)
{
    extern __shared__ char sm[];
    uint32_t smb = smem_u32(sm);
    int tid = threadIdx.x, lane = tid & 31, wid = tid >> 5;
    int wm = wid >> 1, wn = wid & 1;
    int m0 = blockIdx.y * 128, n0 = blockIdx.x * 128;

    float acc[2][8][4];
#pragma unroll
    for (int mt = 0; mt < 2; mt++)
#pragma unroll
        for (int nt = 0; nt < 8; nt++)
#pragma unroll
            for (int e = 0; e < 4; e++) acc[mt][nt][e] = 0.f;

    int a_r = lane & 15, a_c = (lane >> 4) << 3;
    int b_r = (lane & 7) + ((lane >> 4) << 3), b_c = ((lane >> 3) & 1) << 3;

    auto issue = [&](int s, int kc) {
#pragma unroll
        for (int i = 0; i < 2; i++) {
            int idx = tid + i * 256;
            int r = idx >> 2, c = (idx & 3) << 3;
            uint32_t so = (uint32_t)(r * 40 + c) * 2;
            uint32_t sb = smb + s * KP_STAGE;
            size_t ga = (size_t)(m0 + r) * C_ + kc * 32 + c;
            size_t gb = (size_t)(n0 + r) * C_ + kc * 32 + c;
            cp16(sb + KP_AH + so, ahi_g + ga);
            cp16(sb + KP_AL + so, alo_g + ga);
            cp16(sb + KP_BH + so, bhi_g + gb);
            cp16(sb + KP_BL + so, blo_g + gb);
        }
    };

    issue(0, 0);
    asm volatile("cp.async.commit_group;");

    for (int kc = 0; kc < 32; kc++) {
        int cur = kc & 1;
        if (kc + 1 < 32) {
            issue(cur ^ 1, kc + 1);
            asm volatile("cp.async.commit_group;");
            asm volatile("cp.async.wait_group 1;");
        } else {
            asm volatile("cp.async.wait_group 0;");
        }
        __syncthreads();

        uint32_t base = smb + cur * KP_STAGE;
#pragma unroll
        for (int ks = 0; ks < 2; ks++) {
            int k0 = ks * 16;
            uint32_t Ah[2][4], Al[2][4], Bf[4][4];
#pragma unroll
            for (int mt = 0; mt < 2; mt++) {
                ldsm4(Ah[mt], base + KP_AH + ((wm * 32 + mt * 16 + a_r) * 40 + k0 + a_c) * 2);
                ldsm4(Al[mt], base + KP_AL + ((wm * 32 + mt * 16 + a_r) * 40 + k0 + a_c) * 2);
            }
#pragma unroll
            for (int p = 0; p < 4; p++)
                ldsm4(Bf[p], base + KP_BH + ((wn * 64 + p * 16 + b_r) * 40 + k0 + b_c) * 2);
#pragma unroll
            for (int mt = 0; mt < 2; mt++)
#pragma unroll
                for (int p = 0; p < 4; p++) {
                    mma16816(acc[mt][2 * p],     Ah[mt], Bf[p][0], Bf[p][1]);
                    mma16816(acc[mt][2 * p + 1], Ah[mt], Bf[p][2], Bf[p][3]);
                    mma16816(acc[mt][2 * p],     Al[mt], Bf[p][0], Bf[p][1]);
                    mma16816(acc[mt][2 * p + 1], Al[mt], Bf[p][2], Bf[p][3]);
                }
#pragma unroll
            for (int p = 0; p < 4; p++)
                ldsm4(Bf[p], base + KP_BL + ((wn * 64 + p * 16 + b_r) * 40 + k0 + b_c) * 2);
#pragma unroll
            for (int mt = 0; mt < 2; mt++)
#pragma unroll
                for (int p = 0; p < 4; p++) {
                    mma16816(acc[mt][2 * p],     Ah[mt], Bf[p][0], Bf[p][1]);
                    mma16816(acc[mt][2 * p + 1], Ah[mt], Bf[p][2], Bf[p][3]);
                }
        }
        __syncthreads();
    }

    int gid = lane >> 2, lid2 = (lane & 3) * 2;
#pragma unroll
    for (int mt = 0; mt < 2; mt++)
#pragma unroll
        for (int nt = 0; nt < 8; nt++) {
            int row = m0 + wm * 32 + mt * 16 + gid;
            int col = n0 + wn * 64 + nt * 8 + lid2;
            bf16 h0, h1, h2, h3, l0, l1, l2, l3;
            split_bf16(acc[mt][nt][0], h0, l0);
            split_bf16(acc[mt][nt][1], h1, l1);
            split_bf16(acc[mt][nt][2], h2, l2);
            split_bf16(acc[mt][nt][3], h3, l3);
            *(bf162*)(khi_g + (size_t)row * C_ + col)       = bf162(h0, h1);
            *(bf162*)(klo_g + (size_t)row * C_ + col)       = bf162(l0, l1);
            *(bf162*)(khi_g + (size_t)(row + 8) * C_ + col) = bf162(h2, h3);
            *(bf162*)(klo_g + (size_t)(row + 8) * C_ + col) = bf162(l2, l3);
        }
}

// ---------------- QK^T (tensor) + bias + mask -> e = exp(s), row sums -------
#define QKS_QH 0
#define QKS_QL 9216
#define QKS_KH 18432
#define QKS_KL 36864
#define QKS_MS 55296
#define QKS_LS 55808
#define QKS_SMEM 56064

__global__ __launch_bounds__(256) void qk_tc(
    const bf16* __restrict__ qhi, const bf16* __restrict__ qlo,
    const bf16* __restrict__ khi, const bf16* __restrict__ klo,
    const float* __restrict__ bias, const int* __restrict__ mask,
    float* __restrict__ scores)
{
    extern __shared__ char sm[];
    uint32_t smb = smem_u32(sm);
    int b = blockIdx.z, h = blockIdx.y, q0 = blockIdx.x * 64;
    int tid = threadIdx.x, lane = tid & 31, wid = tid >> 5;
    int wm = wid >> 2, wn = wid & 3;
    int* Ms = (int*)(sm + QKS_MS);
    float* lsum = (float*)(sm + QKS_LS);
    if (tid < 64) lsum[tid] = 0.f;

#pragma unroll
    for (int i = 0; i < 2; i++) {
        int idx = tid + i * 256;
        int r = idx >> 3, c = (idx & 7) << 3;
        size_t g = (size_t)(b * NQ_ + q0 + r) * C_ + h * D_ + c;
        *(uint4*)(sm + QKS_QH + (r * 72 + c) * 2) = *(const uint4*)(qhi + g);
        *(uint4*)(sm + QKS_QL + (r * 72 + c) * 2) = *(const uint4*)(qlo + g);
    }
    __syncthreads();

    int a_r = lane & 15, a_c = (lane >> 4) << 3;
    int b_r = (lane & 7) + ((lane >> 4) << 3), b_c = ((lane >> 3) & 1) << 3;
    int gid = lane >> 2, lid2 = (lane & 3) * 2;

    uint32_t Qh[2][4][4], Ql[2][4][4];
#pragma unroll
    for (int mt = 0; mt < 2; mt++)
#pragma unroll
        for (int ks = 0; ks < 4; ks++) {
            ldsm4(Qh[mt][ks], smb + QKS_QH + ((wm * 32 + mt * 16 + a_r) * 72 + ks * 16 + a_c) * 2);
            ldsm4(Ql[mt][ks], smb + QKS_QL + ((wm * 32 + mt * 16 + a_r) * 72 + ks * 16 + a_c) * 2);
        }

    // packed exp2 constants
    const ull SCL2  = pack2(0.1803368801f, 0.1803368801f);   // 0.125*log2(e)
    const ull L2E2  = pack2(1.44269504f, 1.44269504f);
    const ull CBIG2 = pack2(12582912.f, 12582912.f);          // 1.5*2^23
    const ull CNEG2 = pack2(-12582912.f, -12582912.f);
    const ull NONE2 = pack2(-1.f, -1.f);
    const ull ONE2  = pack2(1.f, 1.f);
    const ull C4P   = pack2(0.0096181291f, 0.0096181291f);
    const ull C3P   = pack2(0.0555041087f, 0.0555041087f);
    const ull C2P   = pack2(0.2402265069f, 0.2402265069f);
    const ull C1P   = pack2(0.6931471806f, 0.6931471806f);

    float rsum[2][2] = { {0.f, 0.f}, {0.f, 0.f} };

    for (int k0 = 0; k0 < NK_; k0 += 128) {
        __syncthreads();
#pragma unroll
        for (int i = 0; i < 4; i++) {
            int idx = tid + i * 256;
            int r = idx >> 3, c = (idx & 7) << 3;
            size_t g = (size_t)(b * NK_ + k0 + r) * C_ + h * D_ + c;
            *(uint4*)(sm + QKS_KH + (r * 72 + c) * 2) = *(const uint4*)(khi + g);
            *(uint4*)(sm + QKS_KL + (r * 72 + c) * 2) = *(const uint4*)(klo + g);
        }
        if (tid < 128) Ms[tid] = mask[b * NK_ + k0 + tid];
        __syncthreads();

        float acc[2][4][4];
#pragma unroll
        for (int mt = 0; mt < 2; mt++)
#pragma unroll
            for (int nf = 0; nf < 4; nf++)
#pragma unroll
                for (int e = 0; e < 4; e++) acc[mt][nf][e] = 0.f;

#pragma unroll
        for (int ks = 0; ks < 4; ks++) {
            uint32_t Bh[2][4], Bl[2][4];
#pragma unroll
            for (int np = 0; np < 2; np++) {
                ldsm4(Bh[np], smb + QKS_KH + ((wn * 32 + np * 16 + b_r) * 72 + ks * 16 + b_c) * 2);
                ldsm4(Bl[np], smb + QKS_KL + ((wn * 32 + np * 16 + b_r) * 72 + ks * 16 + b_c) * 2);
            }
#pragma unroll
            for (int mt = 0; mt < 2; mt++)
#pragma unroll
                for (int np = 0; np < 2; np++) {
                    mma16816(acc[mt][2 * np],     Qh[mt][ks], Bh[np][0], Bh[np][1]);
                    mma16816(acc[mt][2 * np + 1], Qh[mt][ks], Bh[np][2], Bh[np][3]);
                    mma16816(acc[mt][2 * np],     Ql[mt][ks], Bh[np][0], Bh[np][1]);
                    mma16816(acc[mt][2 * np + 1], Ql[mt][ks], Bh[np][2], Bh[np][3]);
                    mma16816(acc[mt][2 * np],     Qh[mt][ks], Bl[np][0], Bl[np][1]);
                    mma16816(acc[mt][2 * np + 1], Qh[mt][ks], Bl[np][2], Bl[np][3]);
                }
        }

#pragma unroll
        for (int mt = 0; mt < 2; mt++)
#pragma unroll
            for (int nf = 0; nf < 4; nf++) {
                int cl = wn * 32 + nf * 8 + lid2;
                int col = k0 + cl;
                int msk0 = Ms[cl], msk1 = Ms[cl + 1];
                size_t row0 = ((size_t)((b * H_ + h) * NQ_) + q0 + wm * 32 + mt * 16 + gid) * NK_;
                size_t row1 = row0 + (size_t)8 * NK_;
                float2 bv0 = *(const float2*)(bias + row0 + col);
                float2 bv1 = *(const float2*)(bias + row1 + col);

                // row0 pair: polynomial exp2 on the FMA pipe (packed f32x2)
                ull acc01 = pack2(acc[mt][nf][0], acc[mt][nf][1]);
                ull b01   = pack2(bv0.x, bv0.y);
                ull t2 = fma2(acc01, SCL2, fma2(b01, L2E2, 0ULL));
                ull m2 = add2(t2, CBIG2);
                ull n2 = add2(m2, CNEG2);
                ull f2 = fma2(n2, NONE2, t2);          // f = t - round(t)
                ull p2 = fma2(f2, C4P, C3P);
                p2 = fma2(f2, p2, C2P);
                p2 = fma2(f2, p2, C1P);
                p2 = fma2(f2, p2, ONE2);
                float2 mf = unpack2(m2);
                float2 pf = unpack2(p2);
                float e00 = msk0 ? 0.f : __int_as_float(
                    __float_as_int(pf.x) + (__float_as_int(mf.x) << 23));
                float e01 = msk1 ? 0.f : __int_as_float(
                    __float_as_int(pf.y) + (__float_as_int(mf.y) << 23));

                // row1 pair: MUFU
                float e10 = msk0 ? 0.f : __expf(acc[mt][nf][2] * 0.125f + bv1.x);
                float e11 = msk1 ? 0.f : __expf(acc[mt][nf][3] * 0.125f + bv1.y);

                *(float2*)(scores + row0 + col) = make_float2(e00, e01);
                *(float2*)(scores + row1 + col) = make_float2(e10, e11);
                rsum[mt][0] += e00 + e01;
                rsum[mt][1] += e10 + e11;
            }
    }

#pragma unroll
    for (int mt = 0; mt < 2; mt++)
#pragma unroll
        for (int rr = 0; rr < 2; rr++) {
            float v = rsum[mt][rr];
            v += __shfl_xor_sync(0xffffffffu, v, 1);
            v += __shfl_xor_sync(0xffffffffu, v, 2);
            if ((lane & 3) == 0)
                atomicAdd(&lsum[wm * 32 + mt * 16 + gid + rr * 8], v);
        }
    __syncthreads();
    if (tid < 64)
        g_l[(b * H_ + h) * NQ_ + q0 + tid] = lsum[tid];
}

// ---------------- A@V (tensor) + normalize + attn write + residual ----------
#define AVS_PH 0
#define AVS_PL 17408
#define AVS_VH 34816
#define AVS_VL 53248
#define AVS_LI 71680
#define AVS_SMEM 71936

__global__ __launch_bounds__(256) void av_tc(
    const float* __restrict__ scores_in,
    const bf16* __restrict__ vhi, const bf16* __restrict__ vlo,
    const float* __restrict__ query,
    float* __restrict__ attn_out, float* __restrict__ out0)
{
    extern __shared__ char sm[];
    uint32_t smb = smem_u32(sm);
    int b = blockIdx.z, h = blockIdx.y, q0 = blockIdx.x * 64;
    int tid = threadIdx.x, lane = tid & 31, wid = tid >> 5;
    int wm = wid >> 2, wn = wid & 3;
    float* Li = (float*)(sm + AVS_LI);
    if (tid < 64)
        Li[tid] = 1.0f / g_l[(b * H_ + h) * NQ_ + q0 + tid];

    float acc[2][2][4];
#pragma unroll
    for (int mt = 0; mt < 2; mt++)
#pragma unroll
        for (int nf = 0; nf < 2; nf++)
#pragma unroll
            for (int e = 0; e < 4; e++) acc[mt][nf][e] = 0.f;

    int a_r = lane & 15, a_c = (lane >> 4) << 3;
    int v_r = (lane & 7) + (((lane >> 3) & 1) << 3), v_c = (lane >> 4) << 3;

    for (int k0 = 0; k0 < NK_; k0 += 128) {
        __syncthreads();
#pragma unroll
        for (int i = 0; i < 8; i++) {
            int idx = tid + i * 256;
            int r = idx >> 5, cq = (idx & 31) * 4;
            size_t ga = ((size_t)((b * H_ + h) * NQ_) + q0 + r) * NK_ + k0 + cq;
            float4 e = *(const float4*)(scores_in + ga);
            float li = Li[r];
            float4 p = make_float4(e.x * li, e.y * li, e.z * li, e.w * li);
            *(float4*)(attn_out + ga) = p;
            bf16 h0, h1, h2, h3, l0, l1, l2, l3;
            split_bf16(p.x, h0, l0); split_bf16(p.y, h1, l1);
            split_bf16(p.z, h2, l2); split_bf16(p.w, h3, l3);
            uint32_t so = (uint32_t)(r * 136 + cq) * 2;
            *(bf162*)(sm + AVS_PH + so)     = bf162(h0, h1);
            *(bf162*)(sm + AVS_PH + so + 4) = bf162(h2, h3);
            *(bf162*)(sm + AVS_PL + so)     = bf162(l0, l1);
            *(bf162*)(sm + AVS_PL + so + 4) = bf162(l2, l3);
        }
#pragma unroll
        for (int i = 0; i < 4; i++) {
            int idx = tid + i * 256;
            int r = idx >> 3, c = (idx & 7) << 3;
            size_t g = (size_t)(b * NK_ + k0 + r) * C_ + h * D_ + c;
            *(uint4*)(sm + AVS_VH + (r * 72 + c) * 2) = *(const uint4*)(vhi + g);
            *(uint4*)(sm + AVS_VL + (r * 72 + c) * 2) = *(const uint4*)(vlo + g);
        }
        __syncthreads();

#pragma unroll
        for (int ks = 0; ks < 8; ks++) {
            uint32_t Pf[2][4], Pl[2][4], Bh[4], Bl[4];
#pragma unroll
            for (int mt = 0; mt < 2; mt++) {
                ldsm4(Pf[mt], smb + AVS_PH + ((wm * 32 + mt * 16 + a_r) * 136 + ks * 16 + a_c) * 2);
                ldsm4(Pl[mt], smb + AVS_PL + ((wm * 32 + mt * 16 + a_r) * 136 + ks * 16 + a_c) * 2);
            }
            ldsm4t(Bh, smb + AVS_VH + ((ks * 16 + v_r) * 72 + wn * 16 + v_c) * 2);
            ldsm4t(Bl, smb + AVS_VL + ((ks * 16 + v_r) * 72 + wn * 16 + v_c) * 2);
#pragma unroll
            for (int mt = 0; mt < 2; mt++)
#pragma unroll
                for (int nf = 0; nf < 2; nf++) {
                    mma16816(acc[mt][nf], Pf[mt], Bh[nf * 2], Bh[nf * 2 + 1]);
                    mma16816(acc[mt][nf], Pl[mt], Bh[nf * 2], Bh[nf * 2 + 1]);
                    mma16816(acc[mt][nf], Pf[mt], Bl[nf * 2], Bl[nf * 2 + 1]);
                }
        }
    }

    if (out0) {
        int gid = lane >> 2, lid2 = (lane & 3) * 2;
#pragma unroll
        for (int mt = 0; mt < 2; mt++)
#pragma unroll
            for (int nf = 0; nf < 2; nf++) {
                int row = b * NQ_ + q0 + wm * 32 + mt * 16 + gid;
                int col = h * D_ + wn * 16 + nf * 8 + lid2;
                float2 qv0 = *(const float2*)(query + (size_t)row * C_ + col);
                float2 qv1 = *(const float2*)(query + (size_t)(row + 8) * C_ + col);
                *(float2*)(out0 + (size_t)row * C_ + col) =
                    make_float2(qv0.x + acc[mt][nf][0], qv0.y + acc[mt][nf][1]);
                *(float2*)(out0 + (size_t)(row + 8) * C_ + col) =
                    make_float2(qv1.x + acc[mt][nf][2], qv1.y + acc[mt][nf][3]);
            }
    }
}

// ---------------- host ------------------------------------------------------
extern "C" void kernel_launch(void* const* d_in, const int* in_sizes, int n_in,
                              void* d_out, int out_size)
{
    const float* query  = (const float*)d_in[0];
    const float* memory = (const float*)d_in[1];
    const float* qpos   = (const float*)d_in[2];
    const float* mpos   = (const float*)d_in[3];
    const float* bias   = (const float*)d_in[4];
    const int*   mask   = (const int*)d_in[5];
    const float* Wk     = (const float*)d_in[6];
    const float* lnqw   = (const float*)d_in[7];
    const float* lnqb   = (const float*)d_in[8];
    const float* lnkw   = (const float*)d_in[9];
    const float* lnkb   = (const float*)d_in[10];
    (void)in_sizes; (void)n_in;

    float* out = (float*)d_out;
    const long long OUT0 = (long long)B_ * NQ_ * C_;
    const long long ATT  = (long long)B_ * H_ * NQ_ * NK_;

    float* out0 = nullptr;
    float* attn = nullptr;
    if ((long long)out_size >= OUT0 + ATT) { out0 = out; attn = out + OUT0; }
    else if ((long long)out_size >= ATT)   { attn = out; }
    else {
        out0 = out;
        cudaGetSymbolAddress((void**)&attn, g_scores);
    }

    bf16 *qhi, *qlo, *ahi, *alo, *vhi, *vlo, *khi, *klo, *bhi, *blo;
    cudaGetSymbolAddress((void**)&qhi, g_qhi);
    cudaGetSymbolAddress((void**)&qlo, g_qlo);
    cudaGetSymbolAddress((void**)&ahi, g_ahi);
    cudaGetSymbolAddress((void**)&alo, g_alo);
    cudaGetSymbolAddress((void**)&vhi, g_vhi);
    cudaGetSymbolAddress((void**)&vlo, g_vlo);
    cudaGetSymbolAddress((void**)&khi, g_khi);
    cudaGetSymbolAddress((void**)&klo, g_klo);
    cudaGetSymbolAddress((void**)&bhi, g_bhi);
    cudaGetSymbolAddress((void**)&blo, g_blo);

    cudaFuncSetAttribute(kproj_mma, cudaFuncAttributeMaxDynamicSharedMemorySize, KP_SMEM);
    cudaFuncSetAttribute(qk_tc,     cudaFuncAttributeMaxDynamicSharedMemorySize, QKS_SMEM);
    cudaFuncSetAttribute(av_tc,     cudaFuncAttributeMaxDynamicSharedMemorySize, AVS_SMEM);

    ln_q_kernel<<<B_ * NQ_, 256>>>(query, lnqw, lnqb, qpos, qhi, qlo);
    ln_k_kernel<<<B_ * NK_, 256>>>(memory, lnkw, lnkb, mpos, vhi, vlo, ahi, alo);
    wconv_kernel<<<C_ * C_ / 1024, 256>>>(Wk, bhi, blo);
    {
        dim3 grid(C_ / 128, (B_ * NK_) / 128);
        kproj_mma<<<grid, 256, KP_SMEM>>>(ahi, alo, bhi, blo, khi, klo);
    }
    {
        dim3 grid(NQ_ / 64, H_, B_);
        qk_tc<<<grid, 256, QKS_SMEM>>>(qhi, qlo, khi, klo, bias, mask, attn);
    }
    {
        dim3 grid(NQ_ / 64, H_, B_);
        av_tc<<<grid, 256, AVS_SMEM>>>(attn, vhi, vlo, query, attn, out0);
    }
}